// round 14
// baseline (speedup 1.0000x reference)
#include <cuda_runtime.h>
#include <cuda_fp16.h>
#include <cstdint>
#include <math.h>

#define S_LEN 2048
#define HID   4096
#define NH    32
#define NKV   8
#define HD    128
#define KVDIM (NKV * HD)   // 1024
#define NQKV  (HID + 2 * KVDIM)   // 6144

typedef __half h16;

// ------------------------- device scratch (no allocs allowed) --------------
__device__ float g_Q[(size_t)S_LEN * HID];     // fp32 Q (pre-rope)
__device__ float g_K[(size_t)S_LEN * KVDIM];   // fp32 K (pre-rope)

__device__ h16 g_Xh[S_LEN * HID],  g_Xl[S_LEN * HID];
__device__ h16 g_Wqh[HID * HID],   g_Wql[HID * HID];
__device__ h16 g_Wkh[KVDIM * HID], g_Wkl[KVDIM * HID];
__device__ h16 g_Wvh[KVDIM * HID], g_Wvl[KVDIM * HID];
__device__ h16 g_Wo16[HID * HID];
__device__ h16 g_Qh[S_LEN * HID],   g_Ql[S_LEN * HID];
__device__ h16 g_Kh[S_LEN * KVDIM], g_Kl[S_LEN * KVDIM];
__device__ h16 g_V16[S_LEN * KVDIM];
__device__ h16 g_Ah[S_LEN * HID];               // attn out, single fp16

// ------------------------- PTX helpers (sm_80-class only) -------------------
__device__ __forceinline__ uint32_t smem_u32(const void* p) {
    uint32_t a;
    asm("{ .reg .u64 t; cvta.to.shared.u64 t, %1; cvt.u32.u64 %0, t; }" : "=r"(a) : "l"(p));
    return a;
}
#define CP_ASYNC16(dst, src) \
    asm volatile("cp.async.cg.shared.global [%0], [%1], 16;" :: "r"(dst), "l"(src) : "memory")
#define CP_COMMIT()  asm volatile("cp.async.commit_group;" ::: "memory")
#define CP_WAIT1()   asm volatile("cp.async.wait_group 1;" ::: "memory")

#define LDSM4(r0, r1, r2, r3, addr) \
    asm volatile("ldmatrix.sync.aligned.m8n8.x4.shared.b16 {%0,%1,%2,%3}, [%4];" \
                 : "=r"(r0), "=r"(r1), "=r"(r2), "=r"(r3) : "r"(addr))
#define LDSM4T(r0, r1, r2, r3, addr) \
    asm volatile("ldmatrix.sync.aligned.m8n8.x4.trans.shared.b16 {%0,%1,%2,%3}, [%4];" \
                 : "=r"(r0), "=r"(r1), "=r"(r2), "=r"(r3) : "r"(addr))

__device__ __forceinline__ void mma16816(float* c, const uint32_t* a,
                                         uint32_t b0, uint32_t b1) {
    asm volatile(
        "mma.sync.aligned.m16n8k16.row.col.f32.f16.f16.f32 "
        "{%0,%1,%2,%3}, {%4,%5,%6,%7}, {%8,%9}, {%0,%1,%2,%3};"
        : "+f"(c[0]), "+f"(c[1]), "+f"(c[2]), "+f"(c[3])
        : "r"(a[0]), "r"(a[1]), "r"(a[2]), "r"(a[3]), "r"(b0), "r"(b1));
}

#define SWZ2(o) ((o) ^ (((o) >> 3) & 0x30))
#define SWZV(o) ((o) ^ (((o) >> 4) & 0x70))

__device__ __forceinline__ uint32_t pack_h2(float a, float b) {
    __half2 t = __floats2half2_rn(a, b);
    return *reinterpret_cast<uint32_t*>(&t);
}

// ------------------------- fused prep: split X/Wq/Wk/Wv, conv Wo ------------
#define PB_X  8192
#define PB_WQ (PB_X + 16384)
#define PB_WK (PB_WQ + 4096)
#define PB_WV (PB_WK + 4096)
#define PB_WO (PB_WV + 16384)

__global__ __launch_bounds__(256) void prep_kernel(const float4* __restrict__ X,
                                                   const float4* __restrict__ Wq,
                                                   const float4* __restrict__ Wk,
                                                   const float4* __restrict__ Wv,
                                                   const float4* __restrict__ Wo)
{
    int b = blockIdx.x;
    const float4* src;
    __half2 *hi, *lo;
    int i;
    bool do_split;
    if (b < PB_X) {
        src = X;  hi = (__half2*)g_Xh;  lo = (__half2*)g_Xl;
        i = b * 256 + threadIdx.x; do_split = true;
    } else if (b < PB_WQ) {
        src = Wq; hi = (__half2*)g_Wqh; lo = (__half2*)g_Wql;
        i = (b - PB_X) * 256 + threadIdx.x; do_split = true;
    } else if (b < PB_WK) {
        src = Wk; hi = (__half2*)g_Wkh; lo = (__half2*)g_Wkl;
        i = (b - PB_WQ) * 256 + threadIdx.x; do_split = true;
    } else if (b < PB_WV) {
        src = Wv; hi = (__half2*)g_Wvh; lo = (__half2*)g_Wvl;
        i = (b - PB_WK) * 256 + threadIdx.x; do_split = true;
    } else {
        src = Wo; hi = (__half2*)g_Wo16; lo = nullptr;
        i = (b - PB_WV) * 256 + threadIdx.x; do_split = false;
    }
    float4 v = src[i];
    h16 h0 = __float2half(v.x), h1 = __float2half(v.y);
    h16 h2 = __float2half(v.z), h3 = __float2half(v.w);
    hi[2 * i]     = __halves2half2(h0, h1);
    hi[2 * i + 1] = __halves2half2(h2, h3);
    if (do_split) {
        lo[2 * i]     = __floats2half2_rn(v.x - __half2float(h0), v.y - __half2float(h1));
        lo[2 * i + 1] = __floats2half2_rn(v.z - __half2float(h2), v.w - __half2float(h3));
    }
}

// ======================== fused QKV gemm3: 3-product, BKE=32 ================
#define BM 128
#define BN 128
#define BKE 32
#define TSZ 8192
#define G_AH 0
#define G_AL 8192
#define G_BH 16384
#define G_BL 24576
#define STG  32768
#define NST  3
#define GEMM3_SMEM (NST * STG)

__device__ __forceinline__ void issue_qkv_part(int j, int part, int tid,
                                               int m0, int n0,
                                               const h16* Bh, const h16* Bl,
                                               uint32_t sbase)
{
    int k0 = j * BKE;
    uint32_t st = sbase + (j % NST) * STG + part * TSZ;
    const h16* src = (part == 0) ? g_Xh : (part == 1) ? g_Xl : (part == 2) ? Bh : Bl;
    int base = (part < 2) ? m0 : n0;
#pragma unroll
    for (int t = 0; t < 2; t++) {
        int idx = tid + t * 256;
        int row = idx >> 2;
        int ch  = idx & 3;
        uint32_t off = SWZ2((uint32_t)(row * 64 + ch * 16));
        CP_ASYNC16(st + off, src + (size_t)(base + row) * HID + k0 + ch * 8);
    }
}

__global__ __launch_bounds__(256, 2) void gemm3_qkv()
{
    extern __shared__ char smem[];
    const uint32_t sbase = smem_u32(smem);
    const int tid  = threadIdx.x;
    const int lane = tid & 31;
    const int wid  = tid >> 5;
    const int wm   = wid & 3;
    const int wn   = wid >> 2;
    const int m0 = blockIdx.y * BM;
    const int n0g = blockIdx.x * BN;
    const int kchunks = HID / BKE;

    const h16 *Bh, *Bl;
    int n0, tgt;
    if (n0g < HID)              { Bh = g_Wqh; Bl = g_Wql; n0 = n0g;               tgt = 0; }
    else if (n0g < HID + KVDIM) { Bh = g_Wkh; Bl = g_Wkl; n0 = n0g - HID;         tgt = 1; }
    else                        { Bh = g_Wvh; Bl = g_Wvl; n0 = n0g - HID - KVDIM; tgt = 2; }

    float acc[2][8][4];
#pragma unroll
    for (int i = 0; i < 2; i++)
#pragma unroll
        for (int j = 0; j < 8; j++)
#pragma unroll
            for (int r = 0; r < 4; r++) acc[i][j][r] = 0.f;

    uint32_t arowr[2], browr[4];
#pragma unroll
    for (int i = 0; i < 2; i++)
        arowr[i] = (uint32_t)((wm * 32 + i * 16 + (lane & 15)) * 64 + (lane >> 4) * 16);
#pragma unroll
    for (int p = 0; p < 4; p++)
        browr[p] = (uint32_t)((wn * 64 + p * 16 + (lane & 7) + ((lane >> 4) << 3)) * 64 +
                              ((lane >> 3) & 1) * 16);

    for (int j = 0; j < 2; j++) {
#pragma unroll
        for (int part = 0; part < 4; part++)
            issue_qkv_part(j, part, tid, m0, n0, Bh, Bl, sbase);
        CP_COMMIT();
    }

    for (int it = 0; it < kchunks; it++) {
        uint32_t st = sbase + (it % NST) * STG;
        CP_WAIT1();
        __syncthreads();

        int nj = it + 2;
        bool do_issue = (nj < kchunks);

#pragma unroll
        for (int ks = 0; ks < 2; ks++) {
            if (do_issue) {
                issue_qkv_part(nj, 2 * ks, tid, m0, n0, Bh, Bl, sbase);
                issue_qkv_part(nj, 2 * ks + 1, tid, m0, n0, Bh, Bl, sbase);
            }

            uint32_t kb = ks * 32;
            uint32_t ah[2][4], al[2][4];
#pragma unroll
            for (int i = 0; i < 2; i++) {
                uint32_t off = SWZ2(arowr[i] + kb);
                LDSM4(ah[i][0], ah[i][1], ah[i][2], ah[i][3], st + G_AH + off);
                LDSM4(al[i][0], al[i][1], al[i][2], al[i][3], st + G_AL + off);
            }
#pragma unroll
            for (int p = 0; p < 4; p++) {
                uint32_t off = SWZ2(browr[p] + kb);
                uint32_t bh0, bh1, bh2, bh3, bl0, bl1, bl2, bl3;
                LDSM4(bh0, bh1, bh2, bh3, st + G_BH + off);
                LDSM4(bl0, bl1, bl2, bl3, st + G_BL + off);
                // product-major order: RAW distance 4 on every accumulator
                mma16816(acc[0][2 * p],     ah[0], bh0, bh1);
                mma16816(acc[1][2 * p],     ah[1], bh0, bh1);
                mma16816(acc[0][2 * p + 1], ah[0], bh2, bh3);
                mma16816(acc[1][2 * p + 1], ah[1], bh2, bh3);
                mma16816(acc[0][2 * p],     al[0], bh0, bh1);
                mma16816(acc[1][2 * p],     al[1], bh0, bh1);
                mma16816(acc[0][2 * p + 1], al[0], bh2, bh3);
                mma16816(acc[1][2 * p + 1], al[1], bh2, bh3);
                mma16816(acc[0][2 * p],     ah[0], bl0, bl1);
                mma16816(acc[1][2 * p],     ah[1], bl0, bl1);
                mma16816(acc[0][2 * p + 1], ah[0], bl2, bl3);
                mma16816(acc[1][2 * p + 1], ah[1], bl2, bl3);
            }
        }
        CP_COMMIT();
    }

    const int g   = lane >> 2;
    const int tig = lane & 3;
    if (tgt == 0) {
#pragma unroll
        for (int i = 0; i < 2; i++) {
            int row = m0 + wm * 32 + i * 16 + g;
#pragma unroll
            for (int j = 0; j < 8; j++) {
                int col = n0 + wn * 64 + j * 8 + 2 * tig;
                *(float2*)&g_Q[(size_t)row * HID + col] =
                    make_float2(acc[i][j][0], acc[i][j][1]);
                *(float2*)&g_Q[(size_t)(row + 8) * HID + col] =
                    make_float2(acc[i][j][2], acc[i][j][3]);
            }
        }
    } else if (tgt == 1) {
#pragma unroll
        for (int i = 0; i < 2; i++) {
            int row = m0 + wm * 32 + i * 16 + g;
#pragma unroll
            for (int j = 0; j < 8; j++) {
                int col = n0 + wn * 64 + j * 8 + 2 * tig;
                *(float2*)&g_K[(size_t)row * KVDIM + col] =
                    make_float2(acc[i][j][0], acc[i][j][1]);
                *(float2*)&g_K[(size_t)(row + 8) * KVDIM + col] =
                    make_float2(acc[i][j][2], acc[i][j][3]);
            }
        }
    } else {
#pragma unroll
        for (int i = 0; i < 2; i++) {
            int row = m0 + wm * 32 + i * 16 + g;
#pragma unroll
            for (int j = 0; j < 8; j++) {
                int col = n0 + wn * 64 + j * 8 + 2 * tig;
                *(uint32_t*)&g_V16[(size_t)row * KVDIM + col] =
                    pack_h2(acc[i][j][0], acc[i][j][1]);
                *(uint32_t*)&g_V16[(size_t)(row + 8) * KVDIM + col] =
                    pack_h2(acc[i][j][2], acc[i][j][3]);
            }
        }
    }
}

// ======================== gemm1: single-product fp16 (O projection) =========
#define G1_A  0
#define G1_B  8192
#define STG1  16384
#define NST1  3
#define GEMM1_SMEM (NST1 * STG1)

__device__ __forceinline__ void issue_g1_part(int j, int part, int tid,
                                              int m0, int n0, int K,
                                              const h16* A, const h16* B,
                                              uint32_t sbase)
{
    int k0 = j * BKE;
    uint32_t st = sbase + (j % NST1) * STG1 + part * TSZ;
    const h16* src = (part == 0) ? A : B;
    int base = (part == 0) ? m0 : n0;
#pragma unroll
    for (int t = 0; t < 2; t++) {
        int idx = tid + t * 256;
        int row = idx >> 2;
        int ch  = idx & 3;
        uint32_t off = SWZ2((uint32_t)(row * 64 + ch * 16));
        CP_ASYNC16(st + off, src + (size_t)(base + row) * K + k0 + ch * 8);
    }
}

__global__ __launch_bounds__(256, 2) void gemm1(const h16* __restrict__ A,
                                                const h16* __restrict__ B,
                                                float* __restrict__ C,
                                                int M, int N, int K)
{
    extern __shared__ char smem[];
    const uint32_t sbase = smem_u32(smem);
    const int tid  = threadIdx.x;
    const int lane = tid & 31;
    const int wid  = tid >> 5;
    const int wm   = wid & 3;
    const int wn   = wid >> 2;
    const int m0 = blockIdx.y * BM;
    const int n0 = blockIdx.x * BN;
    const int kchunks = K / BKE;

    float acc[2][8][4];
#pragma unroll
    for (int i = 0; i < 2; i++)
#pragma unroll
        for (int j = 0; j < 8; j++)
#pragma unroll
            for (int r = 0; r < 4; r++) acc[i][j][r] = 0.f;

    uint32_t arowr[2], browr[4];
#pragma unroll
    for (int i = 0; i < 2; i++)
        arowr[i] = (uint32_t)((wm * 32 + i * 16 + (lane & 15)) * 64 + (lane >> 4) * 16);
#pragma unroll
    for (int p = 0; p < 4; p++)
        browr[p] = (uint32_t)((wn * 64 + p * 16 + (lane & 7) + ((lane >> 4) << 3)) * 64 +
                              ((lane >> 3) & 1) * 16);

    for (int j = 0; j < 2; j++) {
#pragma unroll
        for (int part = 0; part < 2; part++)
            issue_g1_part(j, part, tid, m0, n0, K, A, B, sbase);
        CP_COMMIT();
    }

    for (int it = 0; it < kchunks; it++) {
        uint32_t st = sbase + (it % NST1) * STG1;
        CP_WAIT1();
        __syncthreads();

        int nj = it + 2;
        bool do_issue = (nj < kchunks);

#pragma unroll
        for (int ks = 0; ks < 2; ks++) {
            if (do_issue)
                issue_g1_part(nj, ks, tid, m0, n0, K, A, B, sbase);

            uint32_t kb = ks * 32;
            uint32_t a[2][4];
#pragma unroll
            for (int i = 0; i < 2; i++) {
                uint32_t off = SWZ2(arowr[i] + kb);
                LDSM4(a[i][0], a[i][1], a[i][2], a[i][3], st + G1_A + off);
            }
#pragma unroll
            for (int p = 0; p < 4; p++) {
                uint32_t off = SWZ2(browr[p] + kb);
                uint32_t b0, b1, b2, b3;
                LDSM4(b0, b1, b2, b3, st + G1_B + off);
                mma16816(acc[0][2 * p],     a[0], b0, b1);
                mma16816(acc[1][2 * p],     a[1], b0, b1);
                mma16816(acc[0][2 * p + 1], a[0], b2, b3);
                mma16816(acc[1][2 * p + 1], a[1], b2, b3);
            }
        }
        CP_COMMIT();
    }

    const int g   = lane >> 2;
    const int tig = lane & 3;
#pragma unroll
    for (int i = 0; i < 2; i++) {
        int row = m0 + wm * 32 + i * 16 + g;
#pragma unroll
        for (int j = 0; j < 8; j++) {
            int col = n0 + wn * 64 + j * 8 + 2 * tig;
            *(float2*)&C[(size_t)row * N + col] =
                make_float2(acc[i][j][0], acc[i][j][1]);
            *(float2*)&C[(size_t)(row + 8) * N + col] =
                make_float2(acc[i][j][2], acc[i][j][3]);
        }
    }
}

// ---------------------------------------------------------------------------
// Fused RoPE + fp16 hi/lo split.
// ---------------------------------------------------------------------------
__global__ __launch_bounds__(64) void rope_split_kernel()
{
    const int s = blockIdx.x;
    const int h = blockIdx.y;
    const int i = threadIdx.x;

    const float* p;
    h16 *oh, *ol;
    if (h < NH) {
        size_t base = (size_t)s * HID + h * HD;
        p = &g_Q[base]; oh = &g_Qh[base]; ol = &g_Ql[base];
    } else {
        size_t base = (size_t)s * KVDIM + (h - NH) * HD;
        p = &g_K[base]; oh = &g_Kh[base]; ol = &g_Kl[base];
    }

    float freq = __powf(10000.0f, -((float)(2 * i)) / 128.0f);
    float ang  = (float)s * freq;
    float sn, c;
    sincosf(ang, &sn, &c);

    float x1 = p[i];
    float x2 = p[i + 64];
    float y1 = x1 * c - x2 * sn;
    float y2 = x2 * c + x1 * sn;

    h16 h1 = __float2half(y1);
    h16 h2 = __float2half(y2);
    oh[i]      = h1;
    oh[i + 64] = h2;
    ol[i]      = __float2half(y1 - __half2float(h1));
    ol[i + 64] = __float2half(y2 - __half2float(h2));
}

// ---------------------------------------------------------------------------
// HMMA flash attention: QK^T 3-product (product-major order), PV 1-product.
// 3-stage KV pipeline, single sync per tile, reversed qt order.
// ---------------------------------------------------------------------------
#define F_QH 0
#define F_QL 32768
#define F_KV 65536
#define KVSTG 49152
#define FLASH_SMEM (F_KV + 3 * KVSTG)   // 212992

__device__ __forceinline__ void flash_issue_kv(int jt, int tid, int kvh, uint32_t sbase)
{
    uint32_t st = sbase + F_KV + (jt % 3) * KVSTG;
#pragma unroll
    for (int t = 0; t < 12; t++) {
        int idx = tid + t * 256;
        int tile = idx >> 10;                 // 0:Kh 1:Kl 2:V
        int r    = (idx >> 4) & 63;
        int ch   = idx & 15;
        uint32_t off = SWZV((uint32_t)(r * 256 + ch * 16));
        size_t gsrc = (size_t)(jt * 64 + r) * KVDIM + kvh * HD + ch * 8;
        const h16* base = (tile == 0) ? g_Kh : (tile == 1) ? g_Kl : g_V16;
        CP_ASYNC16(st + tile * 16384 + off, base + gsrc);
    }
}

__global__ __launch_bounds__(256, 1) void flash_mma()
{
    extern __shared__ char smem[];
    const uint32_t sbase = smem_u32(smem);
    const int tid  = threadIdx.x;
    const int lane = tid & 31;
    const int wid  = tid >> 5;
    const int qt   = gridDim.x - 1 - blockIdx.x;   // heavy tiles first
    const int h    = blockIdx.y;
    const int kvh  = h >> 2;
    const int q0   = qt * 128;
    const int g    = lane >> 2;
    const int tig  = lane & 3;

#pragma unroll
    for (int t = 0; t < 16; t++) {
        int idx = tid + t * 256;
        int tile = idx >> 11;
        int r    = (idx >> 4) & 127;
        int ch   = idx & 15;
        uint32_t off = SWZV((uint32_t)(r * 256 + ch * 16));
        const h16* src = (tile ? g_Ql : g_Qh) + (size_t)(q0 + r) * HID + h * HD + ch * 8;
        CP_ASYNC16(sbase + (tile ? F_QL : F_QH) + off, src);
    }
    CP_COMMIT();

    const int ntiles = 2 * qt + 2;
    flash_issue_kv(0, tid, kvh, sbase);
    CP_COMMIT();
    flash_issue_kv(1, tid, kvh, sbase);
    CP_COMMIT();

    float of[16][4];
#pragma unroll
    for (int nt = 0; nt < 16; nt++)
#pragma unroll
        for (int r = 0; r < 4; r++) of[nt][r] = 0.f;
    float m0 = -INFINITY, m1 = -INFINITY, l0 = 0.f, l1 = 0.f;

    const float scale = 0.08838834764831845f;
    const int rg0 = q0 + wid * 16 + g;
    const int rg1 = rg0 + 8;

    uint32_t aoffQ = (uint32_t)((wid * 16 + (lane & 15)) * 256 + (lane >> 4) * 16);
    uint32_t boffK[4];
#pragma unroll
    for (int p = 0; p < 4; p++)
        boffK[p] = (uint32_t)((p * 16 + (lane & 7) + ((lane >> 4) << 3)) * 256 +
                              ((lane >> 3) & 1) * 16);
    uint32_t voffr = (uint32_t)(((lane & 7) + ((lane >> 3) & 1) * 8) * 256 +
                                (lane >> 4) * 16);

    for (int jt = 0; jt < ntiles; jt++) {
        uint32_t st = sbase + F_KV + (jt % 3) * KVSTG;
        CP_WAIT1();
        __syncthreads();

        int nj = jt + 2;
        if (nj < ntiles)
            flash_issue_kv(nj, tid, kvh, sbase);
        CP_COMMIT();

        // --- S = Qh*Kh^T + Ql*Kh^T + Qh*Kl^T, product-major (RAW dist 8) ---
        float sfrag[8][4];
#pragma unroll
        for (int j = 0; j < 8; j++)
#pragma unroll
            for (int r = 0; r < 4; r++) sfrag[j][r] = 0.f;

#pragma unroll
        for (int ks = 0; ks < 8; ks++) {
            uint32_t kb = ks * 32;
            uint32_t qh[4], ql[4], kh[4][4], kl[4][4];
            uint32_t qo = SWZV(aoffQ + kb);
            LDSM4(qh[0], qh[1], qh[2], qh[3], sbase + F_QH + qo);
            LDSM4(ql[0], ql[1], ql[2], ql[3], sbase + F_QL + qo);
#pragma unroll
            for (int p = 0; p < 4; p++) {
                uint32_t ko = SWZV(boffK[p] + kb);
                LDSM4(kh[p][0], kh[p][1], kh[p][2], kh[p][3], st + 0 + ko);
                LDSM4(kl[p][0], kl[p][1], kl[p][2], kl[p][3], st + 16384 + ko);
            }
#pragma unroll
            for (int j = 0; j < 8; j++)
                mma16816(sfrag[j], qh, kh[j >> 1][(j & 1) << 1], kh[j >> 1][((j & 1) << 1) + 1]);
#pragma unroll
            for (int j = 0; j < 8; j++)
                mma16816(sfrag[j], ql, kh[j >> 1][(j & 1) << 1], kh[j >> 1][((j & 1) << 1) + 1]);
#pragma unroll
            for (int j = 0; j < 8; j++)
                mma16816(sfrag[j], qh, kl[j >> 1][(j & 1) << 1], kl[j >> 1][((j & 1) << 1) + 1]);
        }

#pragma unroll
        for (int j = 0; j < 8; j++) {
            int cg = jt * 64 + j * 8 + 2 * tig;
            float c0 = sfrag[j][0] * scale; if (cg     > rg0) c0 = -INFINITY;
            float c1 = sfrag[j][1] * scale; if (cg + 1 > rg0) c1 = -INFINITY;
            float c2 = sfrag[j][2] * scale; if (cg     > rg1) c2 = -INFINITY;
            float c3 = sfrag[j][3] * scale; if (cg + 1 > rg1) c3 = -INFINITY;
            sfrag[j][0] = c0; sfrag[j][1] = c1; sfrag[j][2] = c2; sfrag[j][3] = c3;
        }

        float mx0 = -INFINITY, mx1 = -INFINITY;
#pragma unroll
        for (int j = 0; j < 8; j++) {
            mx0 = fmaxf(mx0, fmaxf(sfrag[j][0], sfrag[j][1]));
            mx1 = fmaxf(mx1, fmaxf(sfrag[j][2], sfrag[j][3]));
        }
        mx0 = fmaxf(mx0, __shfl_xor_sync(0xffffffffu, mx0, 1));
        mx0 = fmaxf(mx0, __shfl_xor_sync(0xffffffffu, mx0, 2));
        mx1 = fmaxf(mx1, __shfl_xor_sync(0xffffffffu, mx1, 1));
        mx1 = fmaxf(mx1, __shfl_xor_sync(0xffffffffu, mx1, 2));
        float mn0 = fmaxf(m0, mx0);
        float mn1 = fmaxf(m1, mx1);
        float f0 = __expf(m0 - mn0);
        float f1 = __expf(m1 - mn1);

        uint32_t ph0[8], ph1[8];
        float s0 = 0.f, s1 = 0.f;
#pragma unroll
        for (int j = 0; j < 8; j++) {
            float e0 = __expf(sfrag[j][0] - mn0);
            float e1 = __expf(sfrag[j][1] - mn0);
            float e2 = __expf(sfrag[j][2] - mn1);
            float e3 = __expf(sfrag[j][3] - mn1);
            s0 += e0 + e1; s1 += e2 + e3;
            ph0[j] = pack_h2(e0, e1);
            ph1[j] = pack_h2(e2, e3);
        }
        s0 += __shfl_xor_sync(0xffffffffu, s0, 1);
        s0 += __shfl_xor_sync(0xffffffffu, s0, 2);
        s1 += __shfl_xor_sync(0xffffffffu, s1, 1);
        s1 += __shfl_xor_sync(0xffffffffu, s1, 2);
        l0 = l0 * f0 + s0;
        l1 = l1 * f1 + s1;
        m0 = mn0; m1 = mn1;
        if (f0 != 1.f || f1 != 1.f) {
#pragma unroll
            for (int nt = 0; nt < 16; nt++) {
                of[nt][0] *= f0; of[nt][1] *= f0;
                of[nt][2] *= f1; of[nt][3] *= f1;
            }
        }

        // --- O += P*V (single product; RAW dist 16 across kk) ---
#pragma unroll
        for (int kk = 0; kk < 4; kk++) {
            uint32_t ah[4] = {ph0[2 * kk], ph1[2 * kk], ph0[2 * kk + 1], ph1[2 * kk + 1]};
#pragma unroll
            for (int np = 0; np < 8; np++) {
                uint32_t off = SWZV((uint32_t)(kk * 16 * 256) + voffr + (uint32_t)(np * 32));
                uint32_t v0, v1, v2, v3;
                LDSM4T(v0, v1, v2, v3, st + 32768 + off);
                mma16816(of[2 * np],     ah, v0, v1);
                mma16816(of[2 * np + 1], ah, v2, v3);
            }
        }
    }

    float inv0 = 1.f / l0;
    float inv1 = 1.f / l1;
#pragma unroll
    for (int nt = 0; nt < 16; nt++) {
        int col = h * HD + nt * 8 + 2 * tig;
        *(uint32_t*)&g_Ah[(size_t)rg0 * HID + col] =
            pack_h2(of[nt][0] * inv0, of[nt][1] * inv0);
        *(uint32_t*)&g_Ah[(size_t)rg1 * HID + col] =
            pack_h2(of[nt][2] * inv1, of[nt][3] * inv1);
    }
}

// ---------------------------------------------------------------------------
extern "C" void kernel_launch(void* const* d_in, const int* in_sizes, int n_in,
                              void* d_out, int out_size)
{
    const float* X  = (const float*)d_in[0];
    const float* Wq = (const float*)d_in[1];
    const float* Wk = (const float*)d_in[2];
    const float* Wv = (const float*)d_in[3];
    const float* Wo = (const float*)d_in[4];
    float* out = (float*)d_out;

    h16 *Wo16, *Ahp;
    cudaGetSymbolAddress((void**)&Wo16, g_Wo16);
    cudaGetSymbolAddress((void**)&Ahp,  g_Ah);

    cudaFuncSetAttribute(gemm3_qkv, cudaFuncAttributeMaxDynamicSharedMemorySize, GEMM3_SMEM);
    cudaFuncSetAttribute(gemm1, cudaFuncAttributeMaxDynamicSharedMemorySize, GEMM1_SMEM);
    cudaFuncSetAttribute(flash_mma, cudaFuncAttributeMaxDynamicSharedMemorySize, FLASH_SMEM);

    prep_kernel<<<PB_WO, 256>>>((const float4*)X, (const float4*)Wq,
                                (const float4*)Wk, (const float4*)Wv,
                                (const float4*)Wo);

    gemm3_qkv<<<dim3(NQKV / BN, S_LEN / BM), 256, GEMM3_SMEM>>>();

    rope_split_kernel<<<dim3(S_LEN, NH + NKV), 64>>>();

    flash_mma<<<dim3(S_LEN / 128, NH), 256, FLASH_SMEM>>>();

    gemm1<<<dim3(HID / BN, S_LEN / BM), 256, GEMM1_SMEM>>>(Ahp, Wo16, out, S_LEN, HID, HID);
}

// round 15
// speedup vs baseline: 1.0016x; 1.0016x over previous
#include <cuda_runtime.h>
#include <cuda_fp16.h>
#include <cstdint>
#include <math.h>

#define S_LEN 2048
#define HID   4096
#define NH    32
#define NKV   8
#define HD    128
#define KVDIM (NKV * HD)   // 1024
#define NQKV  (HID + 2 * KVDIM)   // 6144

typedef __half h16;

// ------------------------- device scratch (no allocs allowed) --------------
__device__ float g_Q[(size_t)S_LEN * HID];     // fp32 Q (pre-rope)
__device__ float g_K[(size_t)S_LEN * KVDIM];   // fp32 K (pre-rope)

__device__ h16 g_Xh[S_LEN * HID],  g_Xl[S_LEN * HID];
__device__ h16 g_Wqh[HID * HID],   g_Wql[HID * HID];
__device__ h16 g_Wkh[KVDIM * HID], g_Wkl[KVDIM * HID];
__device__ h16 g_Wvh[KVDIM * HID], g_Wvl[KVDIM * HID];
__device__ h16 g_Wo16[HID * HID];
__device__ h16 g_Qh[S_LEN * HID],   g_Ql[S_LEN * HID];
__device__ h16 g_Kh[S_LEN * KVDIM], g_Kl[S_LEN * KVDIM];
__device__ h16 g_V16[S_LEN * KVDIM];
__device__ h16 g_Ah[S_LEN * HID];               // attn out, single fp16

// ------------------------- PTX helpers (sm_80-class only) -------------------
__device__ __forceinline__ uint32_t smem_u32(const void* p) {
    uint32_t a;
    asm("{ .reg .u64 t; cvta.to.shared.u64 t, %1; cvt.u32.u64 %0, t; }" : "=r"(a) : "l"(p));
    return a;
}
#define CP_ASYNC16(dst, src) \
    asm volatile("cp.async.cg.shared.global [%0], [%1], 16;" :: "r"(dst), "l"(src) : "memory")
#define CP_COMMIT()  asm volatile("cp.async.commit_group;" ::: "memory")
#define CP_WAIT1()   asm volatile("cp.async.wait_group 1;" ::: "memory")

#define LDSM4(r0, r1, r2, r3, addr) \
    asm volatile("ldmatrix.sync.aligned.m8n8.x4.shared.b16 {%0,%1,%2,%3}, [%4];" \
                 : "=r"(r0), "=r"(r1), "=r"(r2), "=r"(r3) : "r"(addr))
#define LDSM4T(r0, r1, r2, r3, addr) \
    asm volatile("ldmatrix.sync.aligned.m8n8.x4.trans.shared.b16 {%0,%1,%2,%3}, [%4];" \
                 : "=r"(r0), "=r"(r1), "=r"(r2), "=r"(r3) : "r"(addr))

__device__ __forceinline__ void mma16816(float* c, const uint32_t* a,
                                         uint32_t b0, uint32_t b1) {
    asm volatile(
        "mma.sync.aligned.m16n8k16.row.col.f32.f16.f16.f32 "
        "{%0,%1,%2,%3}, {%4,%5,%6,%7}, {%8,%9}, {%0,%1,%2,%3};"
        : "+f"(c[0]), "+f"(c[1]), "+f"(c[2]), "+f"(c[3])
        : "r"(a[0]), "r"(a[1]), "r"(a[2]), "r"(a[3]), "r"(b0), "r"(b1));
}

#define SWZ2(o) ((o) ^ (((o) >> 3) & 0x30))
#define SWZV(o) ((o) ^ (((o) >> 4) & 0x70))

__device__ __forceinline__ uint32_t pack_h2(float a, float b) {
    __half2 t = __floats2half2_rn(a, b);
    return *reinterpret_cast<uint32_t*>(&t);
}

// ------------------------- fused prep: split X/Wq/Wk/Wv, conv Wo ------------
#define PB_X  8192
#define PB_WQ (PB_X + 16384)
#define PB_WK (PB_WQ + 4096)
#define PB_WV (PB_WK + 4096)
#define PB_WO (PB_WV + 16384)

__global__ __launch_bounds__(256) void prep_kernel(const float4* __restrict__ X,
                                                   const float4* __restrict__ Wq,
                                                   const float4* __restrict__ Wk,
                                                   const float4* __restrict__ Wv,
                                                   const float4* __restrict__ Wo)
{
    int b = blockIdx.x;
    const float4* src;
    __half2 *hi, *lo;
    int i;
    bool do_split;
    if (b < PB_X) {
        src = X;  hi = (__half2*)g_Xh;  lo = (__half2*)g_Xl;
        i = b * 256 + threadIdx.x; do_split = true;
    } else if (b < PB_WQ) {
        src = Wq; hi = (__half2*)g_Wqh; lo = (__half2*)g_Wql;
        i = (b - PB_X) * 256 + threadIdx.x; do_split = true;
    } else if (b < PB_WK) {
        src = Wk; hi = (__half2*)g_Wkh; lo = (__half2*)g_Wkl;
        i = (b - PB_WQ) * 256 + threadIdx.x; do_split = true;
    } else if (b < PB_WV) {
        src = Wv; hi = (__half2*)g_Wvh; lo = (__half2*)g_Wvl;
        i = (b - PB_WK) * 256 + threadIdx.x; do_split = true;
    } else {
        src = Wo; hi = (__half2*)g_Wo16; lo = nullptr;
        i = (b - PB_WV) * 256 + threadIdx.x; do_split = false;
    }
    float4 v = src[i];
    h16 h0 = __float2half(v.x), h1 = __float2half(v.y);
    h16 h2 = __float2half(v.z), h3 = __float2half(v.w);
    hi[2 * i]     = __halves2half2(h0, h1);
    hi[2 * i + 1] = __halves2half2(h2, h3);
    if (do_split) {
        lo[2 * i]     = __floats2half2_rn(v.x - __half2float(h0), v.y - __half2float(h1));
        lo[2 * i + 1] = __floats2half2_rn(v.z - __half2float(h2), v.w - __half2float(h3));
    }
}

// ======================== fused QKV gemm3: 3-product, BKE=32 ================
#define BM 128
#define BN 128
#define BKE 32
#define TSZ 8192
#define G_AH 0
#define G_AL 8192
#define G_BH 16384
#define G_BL 24576
#define STG  32768
#define NST  3
#define GEMM3_SMEM (NST * STG)

__device__ __forceinline__ void issue_qkv_part(int j, int part, int tid,
                                               int m0, int n0,
                                               const h16* Bh, const h16* Bl,
                                               uint32_t sbase)
{
    int k0 = j * BKE;
    uint32_t st = sbase + (j % NST) * STG + part * TSZ;
    const h16* src = (part == 0) ? g_Xh : (part == 1) ? g_Xl : (part == 2) ? Bh : Bl;
    int base = (part < 2) ? m0 : n0;
#pragma unroll
    for (int t = 0; t < 2; t++) {
        int idx = tid + t * 256;
        int row = idx >> 2;
        int ch  = idx & 3;
        uint32_t off = SWZ2((uint32_t)(row * 64 + ch * 16));
        CP_ASYNC16(st + off, src + (size_t)(base + row) * HID + k0 + ch * 8);
    }
}

__global__ __launch_bounds__(256, 2) void gemm3_qkv()
{
    extern __shared__ char smem[];
    const uint32_t sbase = smem_u32(smem);
    const int tid  = threadIdx.x;
    const int lane = tid & 31;
    const int wid  = tid >> 5;
    const int wm   = wid & 3;
    const int wn   = wid >> 2;
    const int m0 = blockIdx.y * BM;
    const int n0g = blockIdx.x * BN;
    const int kchunks = HID / BKE;

    const h16 *Bh, *Bl;
    int n0, tgt;
    if (n0g < HID)              { Bh = g_Wqh; Bl = g_Wql; n0 = n0g;               tgt = 0; }
    else if (n0g < HID + KVDIM) { Bh = g_Wkh; Bl = g_Wkl; n0 = n0g - HID;         tgt = 1; }
    else                        { Bh = g_Wvh; Bl = g_Wvl; n0 = n0g - HID - KVDIM; tgt = 2; }

    float acc[2][8][4];
#pragma unroll
    for (int i = 0; i < 2; i++)
#pragma unroll
        for (int j = 0; j < 8; j++)
#pragma unroll
            for (int r = 0; r < 4; r++) acc[i][j][r] = 0.f;

    uint32_t arowr[2], browr[4];
#pragma unroll
    for (int i = 0; i < 2; i++)
        arowr[i] = (uint32_t)((wm * 32 + i * 16 + (lane & 15)) * 64 + (lane >> 4) * 16);
#pragma unroll
    for (int p = 0; p < 4; p++)
        browr[p] = (uint32_t)((wn * 64 + p * 16 + (lane & 7) + ((lane >> 4) << 3)) * 64 +
                              ((lane >> 3) & 1) * 16);

    for (int j = 0; j < 2; j++) {
#pragma unroll
        for (int part = 0; part < 4; part++)
            issue_qkv_part(j, part, tid, m0, n0, Bh, Bl, sbase);
        CP_COMMIT();
    }

    for (int it = 0; it < kchunks; it++) {
        uint32_t st = sbase + (it % NST) * STG;
        CP_WAIT1();
        __syncthreads();

        int nj = it + 2;
        bool do_issue = (nj < kchunks);

#pragma unroll
        for (int ks = 0; ks < 2; ks++) {
            if (do_issue) {
                issue_qkv_part(nj, 2 * ks, tid, m0, n0, Bh, Bl, sbase);
                issue_qkv_part(nj, 2 * ks + 1, tid, m0, n0, Bh, Bl, sbase);
            }

            uint32_t kb = ks * 32;
            uint32_t ah[2][4], al[2][4];
#pragma unroll
            for (int i = 0; i < 2; i++) {
                uint32_t off = SWZ2(arowr[i] + kb);
                LDSM4(ah[i][0], ah[i][1], ah[i][2], ah[i][3], st + G_AH + off);
                LDSM4(al[i][0], al[i][1], al[i][2], al[i][3], st + G_AL + off);
            }
#pragma unroll
            for (int p = 0; p < 4; p++) {
                uint32_t off = SWZ2(browr[p] + kb);
                uint32_t bh0, bh1, bh2, bh3, bl0, bl1, bl2, bl3;
                LDSM4(bh0, bh1, bh2, bh3, st + G_BH + off);
                LDSM4(bl0, bl1, bl2, bl3, st + G_BL + off);
#pragma unroll
                for (int i = 0; i < 2; i++) {
                    mma16816(acc[i][2 * p],     ah[i], bh0, bh1);
                    mma16816(acc[i][2 * p],     al[i], bh0, bh1);
                    mma16816(acc[i][2 * p],     ah[i], bl0, bl1);
                    mma16816(acc[i][2 * p + 1], ah[i], bh2, bh3);
                    mma16816(acc[i][2 * p + 1], al[i], bh2, bh3);
                    mma16816(acc[i][2 * p + 1], ah[i], bl2, bl3);
                }
            }
        }
        CP_COMMIT();
    }

    const int g   = lane >> 2;
    const int tig = lane & 3;
    if (tgt == 0) {
#pragma unroll
        for (int i = 0; i < 2; i++) {
            int row = m0 + wm * 32 + i * 16 + g;
#pragma unroll
            for (int j = 0; j < 8; j++) {
                int col = n0 + wn * 64 + j * 8 + 2 * tig;
                *(float2*)&g_Q[(size_t)row * HID + col] =
                    make_float2(acc[i][j][0], acc[i][j][1]);
                *(float2*)&g_Q[(size_t)(row + 8) * HID + col] =
                    make_float2(acc[i][j][2], acc[i][j][3]);
            }
        }
    } else if (tgt == 1) {
#pragma unroll
        for (int i = 0; i < 2; i++) {
            int row = m0 + wm * 32 + i * 16 + g;
#pragma unroll
            for (int j = 0; j < 8; j++) {
                int col = n0 + wn * 64 + j * 8 + 2 * tig;
                *(float2*)&g_K[(size_t)row * KVDIM + col] =
                    make_float2(acc[i][j][0], acc[i][j][1]);
                *(float2*)&g_K[(size_t)(row + 8) * KVDIM + col] =
                    make_float2(acc[i][j][2], acc[i][j][3]);
            }
        }
    } else {
#pragma unroll
        for (int i = 0; i < 2; i++) {
            int row = m0 + wm * 32 + i * 16 + g;
#pragma unroll
            for (int j = 0; j < 8; j++) {
                int col = n0 + wn * 64 + j * 8 + 2 * tig;
                *(uint32_t*)&g_V16[(size_t)row * KVDIM + col] =
                    pack_h2(acc[i][j][0], acc[i][j][1]);
                *(uint32_t*)&g_V16[(size_t)(row + 8) * KVDIM + col] =
                    pack_h2(acc[i][j][2], acc[i][j][3]);
            }
        }
    }
}

// ======================== gemm1: single-product fp16 (O projection) =========
#define G1_A  0
#define G1_B  8192
#define STG1  16384
#define NST1  3
#define GEMM1_SMEM (NST1 * STG1)

__device__ __forceinline__ void issue_g1_part(int j, int part, int tid,
                                              int m0, int n0, int K,
                                              const h16* A, const h16* B,
                                              uint32_t sbase)
{
    int k0 = j * BKE;
    uint32_t st = sbase + (j % NST1) * STG1 + part * TSZ;
    const h16* src = (part == 0) ? A : B;
    int base = (part == 0) ? m0 : n0;
#pragma unroll
    for (int t = 0; t < 2; t++) {
        int idx = tid + t * 256;
        int row = idx >> 2;
        int ch  = idx & 3;
        uint32_t off = SWZ2((uint32_t)(row * 64 + ch * 16));
        CP_ASYNC16(st + off, src + (size_t)(base + row) * K + k0 + ch * 8);
    }
}

__global__ __launch_bounds__(256, 2) void gemm1(const h16* __restrict__ A,
                                                const h16* __restrict__ B,
                                                float* __restrict__ C,
                                                int M, int N, int K)
{
    extern __shared__ char smem[];
    const uint32_t sbase = smem_u32(smem);
    const int tid  = threadIdx.x;
    const int lane = tid & 31;
    const int wid  = tid >> 5;
    const int wm   = wid & 3;
    const int wn   = wid >> 2;
    const int m0 = blockIdx.y * BM;
    const int n0 = blockIdx.x * BN;
    const int kchunks = K / BKE;

    float acc[2][8][4];
#pragma unroll
    for (int i = 0; i < 2; i++)
#pragma unroll
        for (int j = 0; j < 8; j++)
#pragma unroll
            for (int r = 0; r < 4; r++) acc[i][j][r] = 0.f;

    uint32_t arowr[2], browr[4];
#pragma unroll
    for (int i = 0; i < 2; i++)
        arowr[i] = (uint32_t)((wm * 32 + i * 16 + (lane & 15)) * 64 + (lane >> 4) * 16);
#pragma unroll
    for (int p = 0; p < 4; p++)
        browr[p] = (uint32_t)((wn * 64 + p * 16 + (lane & 7) + ((lane >> 4) << 3)) * 64 +
                              ((lane >> 3) & 1) * 16);

    for (int j = 0; j < 2; j++) {
#pragma unroll
        for (int part = 0; part < 2; part++)
            issue_g1_part(j, part, tid, m0, n0, K, A, B, sbase);
        CP_COMMIT();
    }

    for (int it = 0; it < kchunks; it++) {
        uint32_t st = sbase + (it % NST1) * STG1;
        CP_WAIT1();
        __syncthreads();

        int nj = it + 2;
        bool do_issue = (nj < kchunks);

#pragma unroll
        for (int ks = 0; ks < 2; ks++) {
            if (do_issue)
                issue_g1_part(nj, ks, tid, m0, n0, K, A, B, sbase);

            uint32_t kb = ks * 32;
            uint32_t a[2][4];
#pragma unroll
            for (int i = 0; i < 2; i++) {
                uint32_t off = SWZ2(arowr[i] + kb);
                LDSM4(a[i][0], a[i][1], a[i][2], a[i][3], st + G1_A + off);
            }
#pragma unroll
            for (int p = 0; p < 4; p++) {
                uint32_t off = SWZ2(browr[p] + kb);
                uint32_t b0, b1, b2, b3;
                LDSM4(b0, b1, b2, b3, st + G1_B + off);
#pragma unroll
                for (int i = 0; i < 2; i++) {
                    mma16816(acc[i][2 * p],     a[i], b0, b1);
                    mma16816(acc[i][2 * p + 1], a[i], b2, b3);
                }
            }
        }
        CP_COMMIT();
    }

    const int g   = lane >> 2;
    const int tig = lane & 3;
#pragma unroll
    for (int i = 0; i < 2; i++) {
        int row = m0 + wm * 32 + i * 16 + g;
#pragma unroll
        for (int j = 0; j < 8; j++) {
            int col = n0 + wn * 64 + j * 8 + 2 * tig;
            *(float2*)&C[(size_t)row * N + col] =
                make_float2(acc[i][j][0], acc[i][j][1]);
            *(float2*)&C[(size_t)(row + 8) * N + col] =
                make_float2(acc[i][j][2], acc[i][j][3]);
        }
    }
}

// ---------------------------------------------------------------------------
// Fused RoPE + fp16 hi/lo split.
// ---------------------------------------------------------------------------
__global__ __launch_bounds__(64) void rope_split_kernel()
{
    const int s = blockIdx.x;
    const int h = blockIdx.y;
    const int i = threadIdx.x;

    const float* p;
    h16 *oh, *ol;
    if (h < NH) {
        size_t base = (size_t)s * HID + h * HD;
        p = &g_Q[base]; oh = &g_Qh[base]; ol = &g_Ql[base];
    } else {
        size_t base = (size_t)s * KVDIM + (h - NH) * HD;
        p = &g_K[base]; oh = &g_Kh[base]; ol = &g_Kl[base];
    }

    float freq = __powf(10000.0f, -((float)(2 * i)) / 128.0f);
    float ang  = (float)s * freq;
    float sn, c;
    sincosf(ang, &sn, &c);

    float x1 = p[i];
    float x2 = p[i + 64];
    float y1 = x1 * c - x2 * sn;
    float y2 = x2 * c + x1 * sn;

    h16 h1 = __float2half(y1);
    h16 h2 = __float2half(y2);
    oh[i]      = h1;
    oh[i + 64] = h2;
    ol[i]      = __float2half(y1 - __half2float(h1));
    ol[i + 64] = __float2half(y2 - __half2float(h2));
}

// ---------------------------------------------------------------------------
// HMMA flash attention: QK^T 3-product (accumulator-major, R12 order),
// PV 1-product. 3-stage KV pipeline, single sync per tile, reversed qt order.
// ---------------------------------------------------------------------------
#define F_QH 0
#define F_QL 32768
#define F_KV 65536
#define KVSTG 49152
#define FLASH_SMEM (F_KV + 3 * KVSTG)   // 212992

__device__ __forceinline__ void flash_issue_kv(int jt, int tid, int kvh, uint32_t sbase)
{
    uint32_t st = sbase + F_KV + (jt % 3) * KVSTG;
#pragma unroll
    for (int t = 0; t < 12; t++) {
        int idx = tid + t * 256;
        int tile = idx >> 10;                 // 0:Kh 1:Kl 2:V
        int r    = (idx >> 4) & 63;
        int ch   = idx & 15;
        uint32_t off = SWZV((uint32_t)(r * 256 + ch * 16));
        size_t gsrc = (size_t)(jt * 64 + r) * KVDIM + kvh * HD + ch * 8;
        const h16* base = (tile == 0) ? g_Kh : (tile == 1) ? g_Kl : g_V16;
        CP_ASYNC16(st + tile * 16384 + off, base + gsrc);
    }
}

__global__ __launch_bounds__(256, 1) void flash_mma()
{
    extern __shared__ char smem[];
    const uint32_t sbase = smem_u32(smem);
    const int tid  = threadIdx.x;
    const int lane = tid & 31;
    const int wid  = tid >> 5;
    const int qt   = gridDim.x - 1 - blockIdx.x;   // heavy tiles first
    const int h    = blockIdx.y;
    const int kvh  = h >> 2;
    const int q0   = qt * 128;
    const int g    = lane >> 2;
    const int tig  = lane & 3;

#pragma unroll
    for (int t = 0; t < 16; t++) {
        int idx = tid + t * 256;
        int tile = idx >> 11;
        int r    = (idx >> 4) & 127;
        int ch   = idx & 15;
        uint32_t off = SWZV((uint32_t)(r * 256 + ch * 16));
        const h16* src = (tile ? g_Ql : g_Qh) + (size_t)(q0 + r) * HID + h * HD + ch * 8;
        CP_ASYNC16(sbase + (tile ? F_QL : F_QH) + off, src);
    }
    CP_COMMIT();

    const int ntiles = 2 * qt + 2;
    flash_issue_kv(0, tid, kvh, sbase);
    CP_COMMIT();
    flash_issue_kv(1, tid, kvh, sbase);
    CP_COMMIT();

    float of[16][4];
#pragma unroll
    for (int nt = 0; nt < 16; nt++)
#pragma unroll
        for (int r = 0; r < 4; r++) of[nt][r] = 0.f;
    float m0 = -INFINITY, m1 = -INFINITY, l0 = 0.f, l1 = 0.f;

    const float scale = 0.08838834764831845f;
    const int rg0 = q0 + wid * 16 + g;
    const int rg1 = rg0 + 8;

    uint32_t aoffQ = (uint32_t)((wid * 16 + (lane & 15)) * 256 + (lane >> 4) * 16);
    uint32_t boffK[4];
#pragma unroll
    for (int p = 0; p < 4; p++)
        boffK[p] = (uint32_t)((p * 16 + (lane & 7) + ((lane >> 4) << 3)) * 256 +
                              ((lane >> 3) & 1) * 16);
    uint32_t voffr = (uint32_t)(((lane & 7) + ((lane >> 3) & 1) * 8) * 256 +
                                (lane >> 4) * 16);

    for (int jt = 0; jt < ntiles; jt++) {
        uint32_t st = sbase + F_KV + (jt % 3) * KVSTG;
        CP_WAIT1();
        __syncthreads();

        int nj = jt + 2;
        if (nj < ntiles)
            flash_issue_kv(nj, tid, kvh, sbase);
        CP_COMMIT();

        // --- S = Qh*Kh^T + Ql*Kh^T + Qh*Kl^T (accumulator-major, R12) ---
        float sfrag[8][4];
#pragma unroll
        for (int j = 0; j < 8; j++)
#pragma unroll
            for (int r = 0; r < 4; r++) sfrag[j][r] = 0.f;

#pragma unroll
        for (int ks = 0; ks < 8; ks++) {
            uint32_t kb = ks * 32;
            uint32_t qh[4], ql[4], kh[4][4], kl[4][4];
            uint32_t qo = SWZV(aoffQ + kb);
            LDSM4(qh[0], qh[1], qh[2], qh[3], sbase + F_QH + qo);
            LDSM4(ql[0], ql[1], ql[2], ql[3], sbase + F_QL + qo);
#pragma unroll
            for (int p = 0; p < 4; p++) {
                uint32_t ko = SWZV(boffK[p] + kb);
                LDSM4(kh[p][0], kh[p][1], kh[p][2], kh[p][3], st + 0 + ko);
                LDSM4(kl[p][0], kl[p][1], kl[p][2], kl[p][3], st + 16384 + ko);
            }
#pragma unroll
            for (int j = 0; j < 8; j++) {
                int p = j >> 1;
                int hs = (j & 1) << 1;
                mma16816(sfrag[j], qh, kh[p][hs], kh[p][hs + 1]);
                mma16816(sfrag[j], ql, kh[p][hs], kh[p][hs + 1]);
                mma16816(sfrag[j], qh, kl[p][hs], kl[p][hs + 1]);
            }
        }

#pragma unroll
        for (int j = 0; j < 8; j++) {
            int cg = jt * 64 + j * 8 + 2 * tig;
            float c0 = sfrag[j][0] * scale; if (cg     > rg0) c0 = -INFINITY;
            float c1 = sfrag[j][1] * scale; if (cg + 1 > rg0) c1 = -INFINITY;
            float c2 = sfrag[j][2] * scale; if (cg     > rg1) c2 = -INFINITY;
            float c3 = sfrag[j][3] * scale; if (cg + 1 > rg1) c3 = -INFINITY;
            sfrag[j][0] = c0; sfrag[j][1] = c1; sfrag[j][2] = c2; sfrag[j][3] = c3;
        }

        float mx0 = -INFINITY, mx1 = -INFINITY;
#pragma unroll
        for (int j = 0; j < 8; j++) {
            mx0 = fmaxf(mx0, fmaxf(sfrag[j][0], sfrag[j][1]));
            mx1 = fmaxf(mx1, fmaxf(sfrag[j][2], sfrag[j][3]));
        }
        mx0 = fmaxf(mx0, __shfl_xor_sync(0xffffffffu, mx0, 1));
        mx0 = fmaxf(mx0, __shfl_xor_sync(0xffffffffu, mx0, 2));
        mx1 = fmaxf(mx1, __shfl_xor_sync(0xffffffffu, mx1, 1));
        mx1 = fmaxf(mx1, __shfl_xor_sync(0xffffffffu, mx1, 2));
        float mn0 = fmaxf(m0, mx0);
        float mn1 = fmaxf(m1, mx1);
        float f0 = __expf(m0 - mn0);
        float f1 = __expf(m1 - mn1);

        // P single fp16 (PV 1-product)
        uint32_t ph0[8], ph1[8];
        float s0 = 0.f, s1 = 0.f;
#pragma unroll
        for (int j = 0; j < 8; j++) {
            float e0 = __expf(sfrag[j][0] - mn0);
            float e1 = __expf(sfrag[j][1] - mn0);
            float e2 = __expf(sfrag[j][2] - mn1);
            float e3 = __expf(sfrag[j][3] - mn1);
            s0 += e0 + e1; s1 += e2 + e3;
            ph0[j] = pack_h2(e0, e1);
            ph1[j] = pack_h2(e2, e3);
        }
        s0 += __shfl_xor_sync(0xffffffffu, s0, 1);
        s0 += __shfl_xor_sync(0xffffffffu, s0, 2);
        s1 += __shfl_xor_sync(0xffffffffu, s1, 1);
        s1 += __shfl_xor_sync(0xffffffffu, s1, 2);
        l0 = l0 * f0 + s0;
        l1 = l1 * f1 + s1;
        m0 = mn0; m1 = mn1;
        if (f0 != 1.f || f1 != 1.f) {
#pragma unroll
            for (int nt = 0; nt < 16; nt++) {
                of[nt][0] *= f0; of[nt][1] *= f0;
                of[nt][2] *= f1; of[nt][3] *= f1;
            }
        }

        // --- O += P*V (single product) ---
#pragma unroll
        for (int kk = 0; kk < 4; kk++) {
            uint32_t ah[4] = {ph0[2 * kk], ph1[2 * kk], ph0[2 * kk + 1], ph1[2 * kk + 1]};
#pragma unroll
            for (int np = 0; np < 8; np++) {
                uint32_t off = SWZV((uint32_t)(kk * 16 * 256) + voffr + (uint32_t)(np * 32));
                uint32_t v0, v1, v2, v3;
                LDSM4T(v0, v1, v2, v3, st + 32768 + off);
                mma16816(of[2 * np],     ah, v0, v1);
                mma16816(of[2 * np + 1], ah, v2, v3);
            }
        }
    }

    float inv0 = 1.f / l0;
    float inv1 = 1.f / l1;
#pragma unroll
    for (int nt = 0; nt < 16; nt++) {
        int col = h * HD + nt * 8 + 2 * tig;
        *(uint32_t*)&g_Ah[(size_t)rg0 * HID + col] =
            pack_h2(of[nt][0] * inv0, of[nt][1] * inv0);
        *(uint32_t*)&g_Ah[(size_t)rg1 * HID + col] =
            pack_h2(of[nt][2] * inv1, of[nt][3] * inv1);
    }
}

// ---------------------------------------------------------------------------
extern "C" void kernel_launch(void* const* d_in, const int* in_sizes, int n_in,
                              void* d_out, int out_size)
{
    const float* X  = (const float*)d_in[0];
    const float* Wq = (const float*)d_in[1];
    const float* Wk = (const float*)d_in[2];
    const float* Wv = (const float*)d_in[3];
    const float* Wo = (const float*)d_in[4];
    float* out = (float*)d_out;

    h16 *Wo16, *Ahp;
    cudaGetSymbolAddress((void**)&Wo16, g_Wo16);
    cudaGetSymbolAddress((void**)&Ahp,  g_Ah);

    cudaFuncSetAttribute(gemm3_qkv, cudaFuncAttributeMaxDynamicSharedMemorySize, GEMM3_SMEM);
    cudaFuncSetAttribute(gemm1, cudaFuncAttributeMaxDynamicSharedMemorySize, GEMM1_SMEM);
    cudaFuncSetAttribute(flash_mma, cudaFuncAttributeMaxDynamicSharedMemorySize, FLASH_SMEM);

    prep_kernel<<<PB_WO, 256>>>((const float4*)X, (const float4*)Wq,
                                (const float4*)Wk, (const float4*)Wv,
                                (const float4*)Wo);

    gemm3_qkv<<<dim3(NQKV / BN, S_LEN / BM), 256, GEMM3_SMEM>>>();

    rope_split_kernel<<<dim3(S_LEN, NH + NKV), 64>>>();

    flash_mma<<<dim3(S_LEN / 128, NH), 256, FLASH_SMEM>>>();

    gemm1<<<dim3(HID / BN, S_LEN / BM), 256, GEMM1_SMEM>>>(Ahp, Wo16, out, S_LEN, HID, HID);
}

// round 16
// speedup vs baseline: 1.0229x; 1.0213x over previous
#include <cuda_runtime.h>
#include <cuda_fp16.h>
#include <cstdint>
#include <math.h>

#define S_LEN 2048
#define HID   4096
#define NH    32
#define NKV   8
#define HD    128
#define KVDIM (NKV * HD)   // 1024
#define NQKV  (HID + 2 * KVDIM)   // 6144

typedef __half h16;

// ------------------------- device scratch (no allocs allowed) --------------
__device__ float g_Q[(size_t)S_LEN * HID];     // fp32 Q (pre-rope)
__device__ float g_K[(size_t)S_LEN * KVDIM];   // fp32 K (pre-rope)

__device__ h16 g_Xh[S_LEN * HID],  g_Xl[S_LEN * HID];
__device__ h16 g_Wqh[HID * HID],   g_Wql[HID * HID];
__device__ h16 g_Wkh[KVDIM * HID], g_Wkl[KVDIM * HID];
__device__ h16 g_Wvh[KVDIM * HID], g_Wvl[KVDIM * HID];
__device__ h16 g_Wo16[HID * HID];
__device__ h16 g_Qh[S_LEN * HID],   g_Ql[S_LEN * HID];
__device__ h16 g_Kh[S_LEN * KVDIM], g_Kl[S_LEN * KVDIM];
__device__ h16 g_V16[S_LEN * KVDIM];
__device__ h16 g_Ah[S_LEN * HID];               // attn out, single fp16

// ------------------------- PTX helpers (sm_80-class only) -------------------
__device__ __forceinline__ uint32_t smem_u32(const void* p) {
    uint32_t a;
    asm("{ .reg .u64 t; cvta.to.shared.u64 t, %1; cvt.u32.u64 %0, t; }" : "=r"(a) : "l"(p));
    return a;
}
#define CP_ASYNC16(dst, src) \
    asm volatile("cp.async.cg.shared.global [%0], [%1], 16;" :: "r"(dst), "l"(src) : "memory")
#define CP_COMMIT()  asm volatile("cp.async.commit_group;" ::: "memory")
#define CP_WAIT1()   asm volatile("cp.async.wait_group 1;" ::: "memory")

#define LDSM4(r0, r1, r2, r3, addr) \
    asm volatile("ldmatrix.sync.aligned.m8n8.x4.shared.b16 {%0,%1,%2,%3}, [%4];" \
                 : "=r"(r0), "=r"(r1), "=r"(r2), "=r"(r3) : "r"(addr))
#define LDSM4T(r0, r1, r2, r3, addr) \
    asm volatile("ldmatrix.sync.aligned.m8n8.x4.trans.shared.b16 {%0,%1,%2,%3}, [%4];" \
                 : "=r"(r0), "=r"(r1), "=r"(r2), "=r"(r3) : "r"(addr))

__device__ __forceinline__ void mma16816(float* c, const uint32_t* a,
                                         uint32_t b0, uint32_t b1) {
    asm volatile(
        "mma.sync.aligned.m16n8k16.row.col.f32.f16.f16.f32 "
        "{%0,%1,%2,%3}, {%4,%5,%6,%7}, {%8,%9}, {%0,%1,%2,%3};"
        : "+f"(c[0]), "+f"(c[1]), "+f"(c[2]), "+f"(c[3])
        : "r"(a[0]), "r"(a[1]), "r"(a[2]), "r"(a[3]), "r"(b0), "r"(b1));
}

#define SWZ2(o) ((o) ^ (((o) >> 3) & 0x30))
#define SWZV(o) ((o) ^ (((o) >> 4) & 0x70))

__device__ __forceinline__ uint32_t pack_h2(float a, float b) {
    __half2 t = __floats2half2_rn(a, b);
    return *reinterpret_cast<uint32_t*>(&t);
}

// ------------------------- fused prep: split X/Wq/Wk/Wv, conv Wo ------------
#define PB_X  8192
#define PB_WQ (PB_X + 16384)
#define PB_WK (PB_WQ + 4096)
#define PB_WV (PB_WK + 4096)
#define PB_WO (PB_WV + 16384)

__global__ __launch_bounds__(256) void prep_kernel(const float4* __restrict__ X,
                                                   const float4* __restrict__ Wq,
                                                   const float4* __restrict__ Wk,
                                                   const float4* __restrict__ Wv,
                                                   const float4* __restrict__ Wo)
{
    int b = blockIdx.x;
    const float4* src;
    __half2 *hi, *lo;
    int i;
    bool do_split;
    if (b < PB_X) {
        src = X;  hi = (__half2*)g_Xh;  lo = (__half2*)g_Xl;
        i = b * 256 + threadIdx.x; do_split = true;
    } else if (b < PB_WQ) {
        src = Wq; hi = (__half2*)g_Wqh; lo = (__half2*)g_Wql;
        i = (b - PB_X) * 256 + threadIdx.x; do_split = true;
    } else if (b < PB_WK) {
        src = Wk; hi = (__half2*)g_Wkh; lo = (__half2*)g_Wkl;
        i = (b - PB_WQ) * 256 + threadIdx.x; do_split = true;
    } else if (b < PB_WV) {
        src = Wv; hi = (__half2*)g_Wvh; lo = (__half2*)g_Wvl;
        i = (b - PB_WK) * 256 + threadIdx.x; do_split = true;
    } else {
        src = Wo; hi = (__half2*)g_Wo16; lo = nullptr;
        i = (b - PB_WV) * 256 + threadIdx.x; do_split = false;
    }
    float4 v = src[i];
    h16 h0 = __float2half(v.x), h1 = __float2half(v.y);
    h16 h2 = __float2half(v.z), h3 = __float2half(v.w);
    hi[2 * i]     = __halves2half2(h0, h1);
    hi[2 * i + 1] = __halves2half2(h2, h3);
    if (do_split) {
        lo[2 * i]     = __floats2half2_rn(v.x - __half2float(h0), v.y - __half2float(h1));
        lo[2 * i + 1] = __floats2half2_rn(v.z - __half2float(h2), v.w - __half2float(h3));
    }
}

// ======================== fused QKV gemm3: 3-product, BKE=32 ================
#define BM 128
#define BN 128
#define BKE 32
#define TSZ 8192
#define G_AH 0
#define G_AL 8192
#define G_BH 16384
#define G_BL 24576
#define STG  32768
#define NST  3
#define GEMM3_SMEM (NST * STG)

__device__ __forceinline__ void issue_qkv_part(int j, int part, int tid,
                                               int m0, int n0,
                                               const h16* Bh, const h16* Bl,
                                               uint32_t sbase)
{
    int k0 = j * BKE;
    uint32_t st = sbase + (j % NST) * STG + part * TSZ;
    const h16* src = (part == 0) ? g_Xh : (part == 1) ? g_Xl : (part == 2) ? Bh : Bl;
    int base = (part < 2) ? m0 : n0;
#pragma unroll
    for (int t = 0; t < 2; t++) {
        int idx = tid + t * 256;
        int row = idx >> 2;
        int ch  = idx & 3;
        uint32_t off = SWZ2((uint32_t)(row * 64 + ch * 16));
        CP_ASYNC16(st + off, src + (size_t)(base + row) * HID + k0 + ch * 8);
    }
}

__global__ __launch_bounds__(256, 2) void gemm3_qkv()
{
    extern __shared__ char smem[];
    const uint32_t sbase = smem_u32(smem);
    const int tid  = threadIdx.x;
    const int lane = tid & 31;
    const int wid  = tid >> 5;
    const int wm   = wid & 3;
    const int wn   = wid >> 2;
    const int m0 = blockIdx.y * BM;
    const int n0g = blockIdx.x * BN;
    const int kchunks = HID / BKE;

    const h16 *Bh, *Bl;
    int n0, tgt;
    if (n0g < HID)              { Bh = g_Wqh; Bl = g_Wql; n0 = n0g;               tgt = 0; }
    else if (n0g < HID + KVDIM) { Bh = g_Wkh; Bl = g_Wkl; n0 = n0g - HID;         tgt = 1; }
    else                        { Bh = g_Wvh; Bl = g_Wvl; n0 = n0g - HID - KVDIM; tgt = 2; }

    float acc[2][8][4];
#pragma unroll
    for (int i = 0; i < 2; i++)
#pragma unroll
        for (int j = 0; j < 8; j++)
#pragma unroll
            for (int r = 0; r < 4; r++) acc[i][j][r] = 0.f;

    uint32_t arowr[2], browr[4];
#pragma unroll
    for (int i = 0; i < 2; i++)
        arowr[i] = (uint32_t)((wm * 32 + i * 16 + (lane & 15)) * 64 + (lane >> 4) * 16);
#pragma unroll
    for (int p = 0; p < 4; p++)
        browr[p] = (uint32_t)((wn * 64 + p * 16 + (lane & 7) + ((lane >> 4) << 3)) * 64 +
                              ((lane >> 3) & 1) * 16);

    for (int j = 0; j < 2; j++) {
#pragma unroll
        for (int part = 0; part < 4; part++)
            issue_qkv_part(j, part, tid, m0, n0, Bh, Bl, sbase);
        CP_COMMIT();
    }

    for (int it = 0; it < kchunks; it++) {
        uint32_t st = sbase + (it % NST) * STG;
        CP_WAIT1();
        __syncthreads();

        int nj = it + 2;
        bool do_issue = (nj < kchunks);

#pragma unroll
        for (int ks = 0; ks < 2; ks++) {
            if (do_issue) {
                issue_qkv_part(nj, 2 * ks, tid, m0, n0, Bh, Bl, sbase);
                issue_qkv_part(nj, 2 * ks + 1, tid, m0, n0, Bh, Bl, sbase);
            }

            uint32_t kb = ks * 32;
            uint32_t ah[2][4], al[2][4];
#pragma unroll
            for (int i = 0; i < 2; i++) {
                uint32_t off = SWZ2(arowr[i] + kb);
                LDSM4(ah[i][0], ah[i][1], ah[i][2], ah[i][3], st + G_AH + off);
                LDSM4(al[i][0], al[i][1], al[i][2], al[i][3], st + G_AL + off);
            }
#pragma unroll
            for (int p = 0; p < 4; p++) {
                uint32_t off = SWZ2(browr[p] + kb);
                uint32_t bh0, bh1, bh2, bh3, bl0, bl1, bl2, bl3;
                LDSM4(bh0, bh1, bh2, bh3, st + G_BH + off);
                LDSM4(bl0, bl1, bl2, bl3, st + G_BL + off);
#pragma unroll
                for (int i = 0; i < 2; i++) {
                    mma16816(acc[i][2 * p],     ah[i], bh0, bh1);
                    mma16816(acc[i][2 * p],     al[i], bh0, bh1);
                    mma16816(acc[i][2 * p],     ah[i], bl0, bl1);
                    mma16816(acc[i][2 * p + 1], ah[i], bh2, bh3);
                    mma16816(acc[i][2 * p + 1], al[i], bh2, bh3);
                    mma16816(acc[i][2 * p + 1], ah[i], bl2, bl3);
                }
            }
        }
        CP_COMMIT();
    }

    const int g   = lane >> 2;
    const int tig = lane & 3;
    if (tgt == 0) {
#pragma unroll
        for (int i = 0; i < 2; i++) {
            int row = m0 + wm * 32 + i * 16 + g;
#pragma unroll
            for (int j = 0; j < 8; j++) {
                int col = n0 + wn * 64 + j * 8 + 2 * tig;
                *(float2*)&g_Q[(size_t)row * HID + col] =
                    make_float2(acc[i][j][0], acc[i][j][1]);
                *(float2*)&g_Q[(size_t)(row + 8) * HID + col] =
                    make_float2(acc[i][j][2], acc[i][j][3]);
            }
        }
    } else if (tgt == 1) {
#pragma unroll
        for (int i = 0; i < 2; i++) {
            int row = m0 + wm * 32 + i * 16 + g;
#pragma unroll
            for (int j = 0; j < 8; j++) {
                int col = n0 + wn * 64 + j * 8 + 2 * tig;
                *(float2*)&g_K[(size_t)row * KVDIM + col] =
                    make_float2(acc[i][j][0], acc[i][j][1]);
                *(float2*)&g_K[(size_t)(row + 8) * KVDIM + col] =
                    make_float2(acc[i][j][2], acc[i][j][3]);
            }
        }
    } else {
#pragma unroll
        for (int i = 0; i < 2; i++) {
            int row = m0 + wm * 32 + i * 16 + g;
#pragma unroll
            for (int j = 0; j < 8; j++) {
                int col = n0 + wn * 64 + j * 8 + 2 * tig;
                *(uint32_t*)&g_V16[(size_t)row * KVDIM + col] =
                    pack_h2(acc[i][j][0], acc[i][j][1]);
                *(uint32_t*)&g_V16[(size_t)(row + 8) * KVDIM + col] =
                    pack_h2(acc[i][j][2], acc[i][j][3]);
            }
        }
    }
}

// ======================== gemm1: single-product fp16 (O projection) =========
#define G1_A  0
#define G1_B  8192
#define STG1  16384
#define NST1  3
#define GEMM1_SMEM (NST1 * STG1)

__device__ __forceinline__ void issue_g1_part(int j, int part, int tid,
                                              int m0, int n0, int K,
                                              const h16* A, const h16* B,
                                              uint32_t sbase)
{
    int k0 = j * BKE;
    uint32_t st = sbase + (j % NST1) * STG1 + part * TSZ;
    const h16* src = (part == 0) ? A : B;
    int base = (part == 0) ? m0 : n0;
#pragma unroll
    for (int t = 0; t < 2; t++) {
        int idx = tid + t * 256;
        int row = idx >> 2;
        int ch  = idx & 3;
        uint32_t off = SWZ2((uint32_t)(row * 64 + ch * 16));
        CP_ASYNC16(st + off, src + (size_t)(base + row) * K + k0 + ch * 8);
    }
}

__global__ __launch_bounds__(256, 2) void gemm1(const h16* __restrict__ A,
                                                const h16* __restrict__ B,
                                                float* __restrict__ C,
                                                int M, int N, int K)
{
    extern __shared__ char smem[];
    const uint32_t sbase = smem_u32(smem);
    const int tid  = threadIdx.x;
    const int lane = tid & 31;
    const int wid  = tid >> 5;
    const int wm   = wid & 3;
    const int wn   = wid >> 2;
    const int m0 = blockIdx.y * BM;
    const int n0 = blockIdx.x * BN;
    const int kchunks = K / BKE;

    float acc[2][8][4];
#pragma unroll
    for (int i = 0; i < 2; i++)
#pragma unroll
        for (int j = 0; j < 8; j++)
#pragma unroll
            for (int r = 0; r < 4; r++) acc[i][j][r] = 0.f;

    uint32_t arowr[2], browr[4];
#pragma unroll
    for (int i = 0; i < 2; i++)
        arowr[i] = (uint32_t)((wm * 32 + i * 16 + (lane & 15)) * 64 + (lane >> 4) * 16);
#pragma unroll
    for (int p = 0; p < 4; p++)
        browr[p] = (uint32_t)((wn * 64 + p * 16 + (lane & 7) + ((lane >> 4) << 3)) * 64 +
                              ((lane >> 3) & 1) * 16);

    for (int j = 0; j < 2; j++) {
#pragma unroll
        for (int part = 0; part < 2; part++)
            issue_g1_part(j, part, tid, m0, n0, K, A, B, sbase);
        CP_COMMIT();
    }

    for (int it = 0; it < kchunks; it++) {
        uint32_t st = sbase + (it % NST1) * STG1;
        CP_WAIT1();
        __syncthreads();

        int nj = it + 2;
        bool do_issue = (nj < kchunks);

#pragma unroll
        for (int ks = 0; ks < 2; ks++) {
            if (do_issue)
                issue_g1_part(nj, ks, tid, m0, n0, K, A, B, sbase);

            uint32_t kb = ks * 32;
            uint32_t a[2][4];
#pragma unroll
            for (int i = 0; i < 2; i++) {
                uint32_t off = SWZ2(arowr[i] + kb);
                LDSM4(a[i][0], a[i][1], a[i][2], a[i][3], st + G1_A + off);
            }
#pragma unroll
            for (int p = 0; p < 4; p++) {
                uint32_t off = SWZ2(browr[p] + kb);
                uint32_t b0, b1, b2, b3;
                LDSM4(b0, b1, b2, b3, st + G1_B + off);
#pragma unroll
                for (int i = 0; i < 2; i++) {
                    mma16816(acc[i][2 * p],     a[i], b0, b1);
                    mma16816(acc[i][2 * p + 1], a[i], b2, b3);
                }
            }
        }
        CP_COMMIT();
    }

    const int g   = lane >> 2;
    const int tig = lane & 3;
#pragma unroll
    for (int i = 0; i < 2; i++) {
        int row = m0 + wm * 32 + i * 16 + g;
#pragma unroll
        for (int j = 0; j < 8; j++) {
            int col = n0 + wn * 64 + j * 8 + 2 * tig;
            *(float2*)&C[(size_t)row * N + col] =
                make_float2(acc[i][j][0], acc[i][j][1]);
            *(float2*)&C[(size_t)(row + 8) * N + col] =
                make_float2(acc[i][j][2], acc[i][j][3]);
        }
    }
}

// ---------------------------------------------------------------------------
// Fused RoPE + fp16 hi/lo split.
// ---------------------------------------------------------------------------
__global__ __launch_bounds__(64) void rope_split_kernel()
{
    const int s = blockIdx.x;
    const int h = blockIdx.y;
    const int i = threadIdx.x;

    const float* p;
    h16 *oh, *ol;
    if (h < NH) {
        size_t base = (size_t)s * HID + h * HD;
        p = &g_Q[base]; oh = &g_Qh[base]; ol = &g_Ql[base];
    } else {
        size_t base = (size_t)s * KVDIM + (h - NH) * HD;
        p = &g_K[base]; oh = &g_Kh[base]; ol = &g_Kl[base];
    }

    float freq = __powf(10000.0f, -((float)(2 * i)) / 128.0f);
    float ang  = (float)s * freq;
    float sn, c;
    sincosf(ang, &sn, &c);

    float x1 = p[i];
    float x2 = p[i + 64];
    float y1 = x1 * c - x2 * sn;
    float y2 = x2 * c + x1 * sn;

    h16 h1 = __float2half(y1);
    h16 h2 = __float2half(y2);
    oh[i]      = h1;
    oh[i + 64] = h2;
    ol[i]      = __float2half(y1 - __half2float(h1));
    ol[i + 64] = __float2half(y2 - __half2float(h2));
}

// ---------------------------------------------------------------------------
// HMMA flash attention: QK^T 3-product (accumulator-major), PV 1-product.
// 3-stage KV pipeline, single sync per tile, reversed qt order.
// Exact R12 configuration (unconditional O rescale).
// ---------------------------------------------------------------------------
#define F_QH 0
#define F_QL 32768
#define F_KV 65536
#define KVSTG 49152
#define FLASH_SMEM (F_KV + 3 * KVSTG)   // 212992

__device__ __forceinline__ void flash_issue_kv(int jt, int tid, int kvh, uint32_t sbase)
{
    uint32_t st = sbase + F_KV + (jt % 3) * KVSTG;
#pragma unroll
    for (int t = 0; t < 12; t++) {
        int idx = tid + t * 256;
        int tile = idx >> 10;                 // 0:Kh 1:Kl 2:V
        int r    = (idx >> 4) & 63;
        int ch   = idx & 15;
        uint32_t off = SWZV((uint32_t)(r * 256 + ch * 16));
        size_t gsrc = (size_t)(jt * 64 + r) * KVDIM + kvh * HD + ch * 8;
        const h16* base = (tile == 0) ? g_Kh : (tile == 1) ? g_Kl : g_V16;
        CP_ASYNC16(st + tile * 16384 + off, base + gsrc);
    }
}

__global__ __launch_bounds__(256, 1) void flash_mma()
{
    extern __shared__ char smem[];
    const uint32_t sbase = smem_u32(smem);
    const int tid  = threadIdx.x;
    const int lane = tid & 31;
    const int wid  = tid >> 5;
    const int qt   = gridDim.x - 1 - blockIdx.x;   // heavy tiles first
    const int h    = blockIdx.y;
    const int kvh  = h >> 2;
    const int q0   = qt * 128;
    const int g    = lane >> 2;
    const int tig  = lane & 3;

#pragma unroll
    for (int t = 0; t < 16; t++) {
        int idx = tid + t * 256;
        int tile = idx >> 11;
        int r    = (idx >> 4) & 127;
        int ch   = idx & 15;
        uint32_t off = SWZV((uint32_t)(r * 256 + ch * 16));
        const h16* src = (tile ? g_Ql : g_Qh) + (size_t)(q0 + r) * HID + h * HD + ch * 8;
        CP_ASYNC16(sbase + (tile ? F_QL : F_QH) + off, src);
    }
    CP_COMMIT();

    const int ntiles = 2 * qt + 2;
    flash_issue_kv(0, tid, kvh, sbase);
    CP_COMMIT();
    flash_issue_kv(1, tid, kvh, sbase);
    CP_COMMIT();

    float of[16][4];
#pragma unroll
    for (int nt = 0; nt < 16; nt++)
#pragma unroll
        for (int r = 0; r < 4; r++) of[nt][r] = 0.f;
    float m0 = -INFINITY, m1 = -INFINITY, l0 = 0.f, l1 = 0.f;

    const float scale = 0.08838834764831845f;
    const int rg0 = q0 + wid * 16 + g;
    const int rg1 = rg0 + 8;

    uint32_t aoffQ = (uint32_t)((wid * 16 + (lane & 15)) * 256 + (lane >> 4) * 16);
    uint32_t boffK[4];
#pragma unroll
    for (int p = 0; p < 4; p++)
        boffK[p] = (uint32_t)((p * 16 + (lane & 7) + ((lane >> 4) << 3)) * 256 +
                              ((lane >> 3) & 1) * 16);
    uint32_t voffr = (uint32_t)(((lane & 7) + ((lane >> 3) & 1) * 8) * 256 +
                                (lane >> 4) * 16);

    for (int jt = 0; jt < ntiles; jt++) {
        uint32_t st = sbase + F_KV + (jt % 3) * KVSTG;
        CP_WAIT1();
        __syncthreads();

        int nj = jt + 2;
        if (nj < ntiles)
            flash_issue_kv(nj, tid, kvh, sbase);
        CP_COMMIT();

        // --- S = Qh*Kh^T + Ql*Kh^T + Qh*Kl^T ---
        float sfrag[8][4];
#pragma unroll
        for (int j = 0; j < 8; j++)
#pragma unroll
            for (int r = 0; r < 4; r++) sfrag[j][r] = 0.f;

#pragma unroll
        for (int ks = 0; ks < 8; ks++) {
            uint32_t kb = ks * 32;
            uint32_t qh[4], ql[4], kh[4][4], kl[4][4];
            uint32_t qo = SWZV(aoffQ + kb);
            LDSM4(qh[0], qh[1], qh[2], qh[3], sbase + F_QH + qo);
            LDSM4(ql[0], ql[1], ql[2], ql[3], sbase + F_QL + qo);
#pragma unroll
            for (int p = 0; p < 4; p++) {
                uint32_t ko = SWZV(boffK[p] + kb);
                LDSM4(kh[p][0], kh[p][1], kh[p][2], kh[p][3], st + 0 + ko);
                LDSM4(kl[p][0], kl[p][1], kl[p][2], kl[p][3], st + 16384 + ko);
            }
#pragma unroll
            for (int j = 0; j < 8; j++) {
                int p = j >> 1;
                int hs = (j & 1) << 1;
                mma16816(sfrag[j], qh, kh[p][hs], kh[p][hs + 1]);
                mma16816(sfrag[j], ql, kh[p][hs], kh[p][hs + 1]);
                mma16816(sfrag[j], qh, kl[p][hs], kl[p][hs + 1]);
            }
        }

#pragma unroll
        for (int j = 0; j < 8; j++) {
            int cg = jt * 64 + j * 8 + 2 * tig;
            float c0 = sfrag[j][0] * scale; if (cg     > rg0) c0 = -INFINITY;
            float c1 = sfrag[j][1] * scale; if (cg + 1 > rg0) c1 = -INFINITY;
            float c2 = sfrag[j][2] * scale; if (cg     > rg1) c2 = -INFINITY;
            float c3 = sfrag[j][3] * scale; if (cg + 1 > rg1) c3 = -INFINITY;
            sfrag[j][0] = c0; sfrag[j][1] = c1; sfrag[j][2] = c2; sfrag[j][3] = c3;
        }

        float mx0 = -INFINITY, mx1 = -INFINITY;
#pragma unroll
        for (int j = 0; j < 8; j++) {
            mx0 = fmaxf(mx0, fmaxf(sfrag[j][0], sfrag[j][1]));
            mx1 = fmaxf(mx1, fmaxf(sfrag[j][2], sfrag[j][3]));
        }
        mx0 = fmaxf(mx0, __shfl_xor_sync(0xffffffffu, mx0, 1));
        mx0 = fmaxf(mx0, __shfl_xor_sync(0xffffffffu, mx0, 2));
        mx1 = fmaxf(mx1, __shfl_xor_sync(0xffffffffu, mx1, 1));
        mx1 = fmaxf(mx1, __shfl_xor_sync(0xffffffffu, mx1, 2));
        float mn0 = fmaxf(m0, mx0);
        float mn1 = fmaxf(m1, mx1);
        float f0 = __expf(m0 - mn0);
        float f1 = __expf(m1 - mn1);

        // P single fp16 (PV 1-product)
        uint32_t ph0[8], ph1[8];
        float s0 = 0.f, s1 = 0.f;
#pragma unroll
        for (int j = 0; j < 8; j++) {
            float e0 = __expf(sfrag[j][0] - mn0);
            float e1 = __expf(sfrag[j][1] - mn0);
            float e2 = __expf(sfrag[j][2] - mn1);
            float e3 = __expf(sfrag[j][3] - mn1);
            s0 += e0 + e1; s1 += e2 + e3;
            ph0[j] = pack_h2(e0, e1);
            ph1[j] = pack_h2(e2, e3);
        }
        s0 += __shfl_xor_sync(0xffffffffu, s0, 1);
        s0 += __shfl_xor_sync(0xffffffffu, s0, 2);
        s1 += __shfl_xor_sync(0xffffffffu, s1, 1);
        s1 += __shfl_xor_sync(0xffffffffu, s1, 2);
        l0 = l0 * f0 + s0;
        l1 = l1 * f1 + s1;
        m0 = mn0; m1 = mn1;
#pragma unroll
        for (int nt = 0; nt < 16; nt++) {
            of[nt][0] *= f0; of[nt][1] *= f0;
            of[nt][2] *= f1; of[nt][3] *= f1;
        }

        // --- O += P*V (single product) ---
#pragma unroll
        for (int kk = 0; kk < 4; kk++) {
            uint32_t ah[4] = {ph0[2 * kk], ph1[2 * kk], ph0[2 * kk + 1], ph1[2 * kk + 1]};
#pragma unroll
            for (int np = 0; np < 8; np++) {
                uint32_t off = SWZV((uint32_t)(kk * 16 * 256) + voffr + (uint32_t)(np * 32));
                uint32_t v0, v1, v2, v3;
                LDSM4T(v0, v1, v2, v3, st + 32768 + off);
                mma16816(of[2 * np],     ah, v0, v1);
                mma16816(of[2 * np + 1], ah, v2, v3);
            }
        }
    }

    float inv0 = 1.f / l0;
    float inv1 = 1.f / l1;
#pragma unroll
    for (int nt = 0; nt < 16; nt++) {
        int col = h * HD + nt * 8 + 2 * tig;
        *(uint32_t*)&g_Ah[(size_t)rg0 * HID + col] =
            pack_h2(of[nt][0] * inv0, of[nt][1] * inv0);
        *(uint32_t*)&g_Ah[(size_t)rg1 * HID + col] =
            pack_h2(of[nt][2] * inv1, of[nt][3] * inv1);
    }
}

// ---------------------------------------------------------------------------
extern "C" void kernel_launch(void* const* d_in, const int* in_sizes, int n_in,
                              void* d_out, int out_size)
{
    const float* X  = (const float*)d_in[0];
    const float* Wq = (const float*)d_in[1];
    const float* Wk = (const float*)d_in[2];
    const float* Wv = (const float*)d_in[3];
    const float* Wo = (const float*)d_in[4];
    float* out = (float*)d_out;

    h16 *Wo16, *Ahp;
    cudaGetSymbolAddress((void**)&Wo16, g_Wo16);
    cudaGetSymbolAddress((void**)&Ahp,  g_Ah);

    cudaFuncSetAttribute(gemm3_qkv, cudaFuncAttributeMaxDynamicSharedMemorySize, GEMM3_SMEM);
    cudaFuncSetAttribute(gemm1, cudaFuncAttributeMaxDynamicSharedMemorySize, GEMM1_SMEM);
    cudaFuncSetAttribute(flash_mma, cudaFuncAttributeMaxDynamicSharedMemorySize, FLASH_SMEM);

    prep_kernel<<<PB_WO, 256>>>((const float4*)X, (const float4*)Wq,
                                (const float4*)Wk, (const float4*)Wv,
                                (const float4*)Wo);

    gemm3_qkv<<<dim3(NQKV / BN, S_LEN / BM), 256, GEMM3_SMEM>>>();

    rope_split_kernel<<<dim3(S_LEN, NH + NKV), 64>>>();

    flash_mma<<<dim3(S_LEN / 128, NH), 256, FLASH_SMEM>>>();

    gemm1<<<dim3(HID / BN, S_LEN / BM), 256, GEMM1_SMEM>>>(Ahp, Wo16, out, S_LEN, HID, HID);
}

// round 17
// speedup vs baseline: 1.1247x; 1.0994x over previous
#include <cuda_runtime.h>
#include <cuda_fp16.h>
#include <cstdint>
#include <math.h>

#define S_LEN 2048
#define HID   4096
#define NH    32
#define NKV   8
#define HD    128
#define KVDIM (NKV * HD)   // 1024
#define NQKV  (HID + 2 * KVDIM)   // 6144

typedef __half h16;

// ------------------------- device scratch (no allocs allowed) --------------
__device__ float g_Q[(size_t)S_LEN * HID];     // fp32 Q (pre-rope)
__device__ float g_K[(size_t)S_LEN * KVDIM];   // fp32 K (pre-rope)

__device__ h16 g_Xh[S_LEN * HID],  g_Xl[S_LEN * HID];
__device__ h16 g_Wqh[HID * HID],   g_Wql[HID * HID];
__device__ h16 g_Wkh[KVDIM * HID], g_Wkl[KVDIM * HID];
__device__ h16 g_Wvh[KVDIM * HID], g_Wvl[KVDIM * HID];
__device__ h16 g_Wo16[HID * HID];
__device__ h16 g_Qh[S_LEN * HID],   g_Ql[S_LEN * HID];
__device__ h16 g_Kh[S_LEN * KVDIM], g_Kl[S_LEN * KVDIM];
__device__ h16 g_V16[S_LEN * KVDIM];
__device__ h16 g_Ah[S_LEN * HID];               // attn out, single fp16

// ------------------------- PTX helpers (sm_80-class only) -------------------
__device__ __forceinline__ uint32_t smem_u32(const void* p) {
    uint32_t a;
    asm("{ .reg .u64 t; cvta.to.shared.u64 t, %1; cvt.u32.u64 %0, t; }" : "=r"(a) : "l"(p));
    return a;
}
#define CP_ASYNC16(dst, src) \
    asm volatile("cp.async.cg.shared.global [%0], [%1], 16;" :: "r"(dst), "l"(src) : "memory")
#define CP_COMMIT()  asm volatile("cp.async.commit_group;" ::: "memory")
#define CP_WAIT1()   asm volatile("cp.async.wait_group 1;" ::: "memory")

#define LDSM4(r0, r1, r2, r3, addr) \
    asm volatile("ldmatrix.sync.aligned.m8n8.x4.shared.b16 {%0,%1,%2,%3}, [%4];" \
                 : "=r"(r0), "=r"(r1), "=r"(r2), "=r"(r3) : "r"(addr))
#define LDSM4T(r0, r1, r2, r3, addr) \
    asm volatile("ldmatrix.sync.aligned.m8n8.x4.trans.shared.b16 {%0,%1,%2,%3}, [%4];" \
                 : "=r"(r0), "=r"(r1), "=r"(r2), "=r"(r3) : "r"(addr))

__device__ __forceinline__ void mma16816(float* c, const uint32_t* a,
                                         uint32_t b0, uint32_t b1) {
    asm volatile(
        "mma.sync.aligned.m16n8k16.row.col.f32.f16.f16.f32 "
        "{%0,%1,%2,%3}, {%4,%5,%6,%7}, {%8,%9}, {%0,%1,%2,%3};"
        : "+f"(c[0]), "+f"(c[1]), "+f"(c[2]), "+f"(c[3])
        : "r"(a[0]), "r"(a[1]), "r"(a[2]), "r"(a[3]), "r"(b0), "r"(b1));
}

#define SWZ2(o) ((o) ^ (((o) >> 3) & 0x30))
#define SWZV(o) ((o) ^ (((o) >> 4) & 0x70))

__device__ __forceinline__ uint32_t pack_h2(float a, float b) {
    __half2 t = __floats2half2_rn(a, b);
    return *reinterpret_cast<uint32_t*>(&t);
}

// ------------------------- fused prep: split X/Wq/Wk/Wv, conv Wo ------------
#define PB_X  8192
#define PB_WQ (PB_X + 16384)
#define PB_WK (PB_WQ + 4096)
#define PB_WV (PB_WK + 4096)
#define PB_WO (PB_WV + 16384)

__global__ __launch_bounds__(256) void prep_kernel(const float4* __restrict__ X,
                                                   const float4* __restrict__ Wq,
                                                   const float4* __restrict__ Wk,
                                                   const float4* __restrict__ Wv,
                                                   const float4* __restrict__ Wo)
{
    int b = blockIdx.x;
    const float4* src;
    __half2 *hi, *lo;
    int i;
    bool do_split;
    if (b < PB_X) {
        src = X;  hi = (__half2*)g_Xh;  lo = (__half2*)g_Xl;
        i = b * 256 + threadIdx.x; do_split = true;
    } else if (b < PB_WQ) {
        src = Wq; hi = (__half2*)g_Wqh; lo = (__half2*)g_Wql;
        i = (b - PB_X) * 256 + threadIdx.x; do_split = true;
    } else if (b < PB_WK) {
        src = Wk; hi = (__half2*)g_Wkh; lo = (__half2*)g_Wkl;
        i = (b - PB_WQ) * 256 + threadIdx.x; do_split = true;
    } else if (b < PB_WV) {
        src = Wv; hi = (__half2*)g_Wvh; lo = (__half2*)g_Wvl;
        i = (b - PB_WK) * 256 + threadIdx.x; do_split = true;
    } else {
        src = Wo; hi = (__half2*)g_Wo16; lo = nullptr;
        i = (b - PB_WV) * 256 + threadIdx.x; do_split = false;
    }
    float4 v = src[i];
    h16 h0 = __float2half(v.x), h1 = __float2half(v.y);
    h16 h2 = __float2half(v.z), h3 = __float2half(v.w);
    hi[2 * i]     = __halves2half2(h0, h1);
    hi[2 * i + 1] = __halves2half2(h2, h3);
    if (do_split) {
        lo[2 * i]     = __floats2half2_rn(v.x - __half2float(h0), v.y - __half2float(h1));
        lo[2 * i + 1] = __floats2half2_rn(v.z - __half2float(h2), v.w - __half2float(h3));
    }
}

// ======================== fused QKV gemm3: 3-product, BKE=32 ================
// V-target CTAs (tgt==2) run a 2-product loop (skip Bl entirely).
#define BM 128
#define BN 128
#define BKE 32
#define TSZ 8192
#define G_AH 0
#define G_AL 8192
#define G_BH 16384
#define G_BL 24576
#define STG  32768
#define NST  3
#define GEMM3_SMEM (NST * STG)

__device__ __forceinline__ void issue_qkv_part(int j, int part, int tid,
                                               int m0, int n0,
                                               const h16* Bh, const h16* Bl,
                                               uint32_t sbase)
{
    int k0 = j * BKE;
    uint32_t st = sbase + (j % NST) * STG + part * TSZ;
    const h16* src = (part == 0) ? g_Xh : (part == 1) ? g_Xl : (part == 2) ? Bh : Bl;
    int base = (part < 2) ? m0 : n0;
#pragma unroll
    for (int t = 0; t < 2; t++) {
        int idx = tid + t * 256;
        int row = idx >> 2;
        int ch  = idx & 3;
        uint32_t off = SWZ2((uint32_t)(row * 64 + ch * 16));
        CP_ASYNC16(st + off, src + (size_t)(base + row) * HID + k0 + ch * 8);
    }
}

__global__ __launch_bounds__(256, 2) void gemm3_qkv()
{
    extern __shared__ char smem[];
    const uint32_t sbase = smem_u32(smem);
    const int tid  = threadIdx.x;
    const int lane = tid & 31;
    const int wid  = tid >> 5;
    const int wm   = wid & 3;
    const int wn   = wid >> 2;
    const int m0 = blockIdx.y * BM;
    const int n0g = blockIdx.x * BN;
    const int kchunks = HID / BKE;

    const h16 *Bh, *Bl;
    int n0, tgt;
    if (n0g < HID)              { Bh = g_Wqh; Bl = g_Wql; n0 = n0g;               tgt = 0; }
    else if (n0g < HID + KVDIM) { Bh = g_Wkh; Bl = g_Wkl; n0 = n0g - HID;         tgt = 1; }
    else                        { Bh = g_Wvh; Bl = g_Wvl; n0 = n0g - HID - KVDIM; tgt = 2; }

    float acc[2][8][4];
#pragma unroll
    for (int i = 0; i < 2; i++)
#pragma unroll
        for (int j = 0; j < 8; j++)
#pragma unroll
            for (int r = 0; r < 4; r++) acc[i][j][r] = 0.f;

    uint32_t arowr[2], browr[4];
#pragma unroll
    for (int i = 0; i < 2; i++)
        arowr[i] = (uint32_t)((wm * 32 + i * 16 + (lane & 15)) * 64 + (lane >> 4) * 16);
#pragma unroll
    for (int p = 0; p < 4; p++)
        browr[p] = (uint32_t)((wn * 64 + p * 16 + (lane & 7) + ((lane >> 4) << 3)) * 64 +
                              ((lane >> 3) & 1) * 16);

    if (tgt != 2) {
        // ---------------- 3-product loop (Q/K; identical to R16) -----------
        for (int j = 0; j < 2; j++) {
#pragma unroll
            for (int part = 0; part < 4; part++)
                issue_qkv_part(j, part, tid, m0, n0, Bh, Bl, sbase);
            CP_COMMIT();
        }

        for (int it = 0; it < kchunks; it++) {
            uint32_t st = sbase + (it % NST) * STG;
            CP_WAIT1();
            __syncthreads();

            int nj = it + 2;
            bool do_issue = (nj < kchunks);

#pragma unroll
            for (int ks = 0; ks < 2; ks++) {
                if (do_issue) {
                    issue_qkv_part(nj, 2 * ks, tid, m0, n0, Bh, Bl, sbase);
                    issue_qkv_part(nj, 2 * ks + 1, tid, m0, n0, Bh, Bl, sbase);
                }

                uint32_t kb = ks * 32;
                uint32_t ah[2][4], al[2][4];
#pragma unroll
                for (int i = 0; i < 2; i++) {
                    uint32_t off = SWZ2(arowr[i] + kb);
                    LDSM4(ah[i][0], ah[i][1], ah[i][2], ah[i][3], st + G_AH + off);
                    LDSM4(al[i][0], al[i][1], al[i][2], al[i][3], st + G_AL + off);
                }
#pragma unroll
                for (int p = 0; p < 4; p++) {
                    uint32_t off = SWZ2(browr[p] + kb);
                    uint32_t bh0, bh1, bh2, bh3, bl0, bl1, bl2, bl3;
                    LDSM4(bh0, bh1, bh2, bh3, st + G_BH + off);
                    LDSM4(bl0, bl1, bl2, bl3, st + G_BL + off);
#pragma unroll
                    for (int i = 0; i < 2; i++) {
                        mma16816(acc[i][2 * p],     ah[i], bh0, bh1);
                        mma16816(acc[i][2 * p],     al[i], bh0, bh1);
                        mma16816(acc[i][2 * p],     ah[i], bl0, bl1);
                        mma16816(acc[i][2 * p + 1], ah[i], bh2, bh3);
                        mma16816(acc[i][2 * p + 1], al[i], bh2, bh3);
                        mma16816(acc[i][2 * p + 1], ah[i], bl2, bl3);
                    }
                }
            }
            CP_COMMIT();
        }
    } else {
        // ---------------- 2-product loop (V; no Bl loads, no ah*bl) --------
        for (int j = 0; j < 2; j++) {
#pragma unroll
            for (int part = 0; part < 3; part++)
                issue_qkv_part(j, part, tid, m0, n0, Bh, Bl, sbase);
            CP_COMMIT();
        }

        for (int it = 0; it < kchunks; it++) {
            uint32_t st = sbase + (it % NST) * STG;
            CP_WAIT1();
            __syncthreads();

            int nj = it + 2;
            bool do_issue = (nj < kchunks);

#pragma unroll
            for (int ks = 0; ks < 2; ks++) {
                if (do_issue) {
                    if (ks == 0) {
                        issue_qkv_part(nj, 0, tid, m0, n0, Bh, Bl, sbase);
                        issue_qkv_part(nj, 1, tid, m0, n0, Bh, Bl, sbase);
                    } else {
                        issue_qkv_part(nj, 2, tid, m0, n0, Bh, Bl, sbase);
                    }
                }

                uint32_t kb = ks * 32;
                uint32_t ah[2][4], al[2][4];
#pragma unroll
                for (int i = 0; i < 2; i++) {
                    uint32_t off = SWZ2(arowr[i] + kb);
                    LDSM4(ah[i][0], ah[i][1], ah[i][2], ah[i][3], st + G_AH + off);
                    LDSM4(al[i][0], al[i][1], al[i][2], al[i][3], st + G_AL + off);
                }
#pragma unroll
                for (int p = 0; p < 4; p++) {
                    uint32_t off = SWZ2(browr[p] + kb);
                    uint32_t bh0, bh1, bh2, bh3;
                    LDSM4(bh0, bh1, bh2, bh3, st + G_BH + off);
#pragma unroll
                    for (int i = 0; i < 2; i++) {
                        mma16816(acc[i][2 * p],     ah[i], bh0, bh1);
                        mma16816(acc[i][2 * p],     al[i], bh0, bh1);
                        mma16816(acc[i][2 * p + 1], ah[i], bh2, bh3);
                        mma16816(acc[i][2 * p + 1], al[i], bh2, bh3);
                    }
                }
            }
            CP_COMMIT();
        }
    }

    const int g   = lane >> 2;
    const int tig = lane & 3;
    if (tgt == 0) {
#pragma unroll
        for (int i = 0; i < 2; i++) {
            int row = m0 + wm * 32 + i * 16 + g;
#pragma unroll
            for (int j = 0; j < 8; j++) {
                int col = n0 + wn * 64 + j * 8 + 2 * tig;
                *(float2*)&g_Q[(size_t)row * HID + col] =
                    make_float2(acc[i][j][0], acc[i][j][1]);
                *(float2*)&g_Q[(size_t)(row + 8) * HID + col] =
                    make_float2(acc[i][j][2], acc[i][j][3]);
            }
        }
    } else if (tgt == 1) {
#pragma unroll
        for (int i = 0; i < 2; i++) {
            int row = m0 + wm * 32 + i * 16 + g;
#pragma unroll
            for (int j = 0; j < 8; j++) {
                int col = n0 + wn * 64 + j * 8 + 2 * tig;
                *(float2*)&g_K[(size_t)row * KVDIM + col] =
                    make_float2(acc[i][j][0], acc[i][j][1]);
                *(float2*)&g_K[(size_t)(row + 8) * KVDIM + col] =
                    make_float2(acc[i][j][2], acc[i][j][3]);
            }
        }
    } else {
#pragma unroll
        for (int i = 0; i < 2; i++) {
            int row = m0 + wm * 32 + i * 16 + g;
#pragma unroll
            for (int j = 0; j < 8; j++) {
                int col = n0 + wn * 64 + j * 8 + 2 * tig;
                *(uint32_t*)&g_V16[(size_t)row * KVDIM + col] =
                    pack_h2(acc[i][j][0], acc[i][j][1]);
                *(uint32_t*)&g_V16[(size_t)(row + 8) * KVDIM + col] =
                    pack_h2(acc[i][j][2], acc[i][j][3]);
            }
        }
    }
}

// ======================== gemm1: single-product fp16 (O projection) =========
#define G1_A  0
#define G1_B  8192
#define STG1  16384
#define NST1  3
#define GEMM1_SMEM (NST1 * STG1)

__device__ __forceinline__ void issue_g1_part(int j, int part, int tid,
                                              int m0, int n0, int K,
                                              const h16* A, const h16* B,
                                              uint32_t sbase)
{
    int k0 = j * BKE;
    uint32_t st = sbase + (j % NST1) * STG1 + part * TSZ;
    const h16* src = (part == 0) ? A : B;
    int base = (part == 0) ? m0 : n0;
#pragma unroll
    for (int t = 0; t < 2; t++) {
        int idx = tid + t * 256;
        int row = idx >> 2;
        int ch  = idx & 3;
        uint32_t off = SWZ2((uint32_t)(row * 64 + ch * 16));
        CP_ASYNC16(st + off, src + (size_t)(base + row) * K + k0 + ch * 8);
    }
}

__global__ __launch_bounds__(256, 2) void gemm1(const h16* __restrict__ A,
                                                const h16* __restrict__ B,
                                                float* __restrict__ C,
                                                int M, int N, int K)
{
    extern __shared__ char smem[];
    const uint32_t sbase = smem_u32(smem);
    const int tid  = threadIdx.x;
    const int lane = tid & 31;
    const int wid  = tid >> 5;
    const int wm   = wid & 3;
    const int wn   = wid >> 2;
    const int m0 = blockIdx.y * BM;
    const int n0 = blockIdx.x * BN;
    const int kchunks = K / BKE;

    float acc[2][8][4];
#pragma unroll
    for (int i = 0; i < 2; i++)
#pragma unroll
        for (int j = 0; j < 8; j++)
#pragma unroll
            for (int r = 0; r < 4; r++) acc[i][j][r] = 0.f;

    uint32_t arowr[2], browr[4];
#pragma unroll
    for (int i = 0; i < 2; i++)
        arowr[i] = (uint32_t)((wm * 32 + i * 16 + (lane & 15)) * 64 + (lane >> 4) * 16);
#pragma unroll
    for (int p = 0; p < 4; p++)
        browr[p] = (uint32_t)((wn * 64 + p * 16 + (lane & 7) + ((lane >> 4) << 3)) * 64 +
                              ((lane >> 3) & 1) * 16);

    for (int j = 0; j < 2; j++) {
#pragma unroll
        for (int part = 0; part < 2; part++)
            issue_g1_part(j, part, tid, m0, n0, K, A, B, sbase);
        CP_COMMIT();
    }

    for (int it = 0; it < kchunks; it++) {
        uint32_t st = sbase + (it % NST1) * STG1;
        CP_WAIT1();
        __syncthreads();

        int nj = it + 2;
        bool do_issue = (nj < kchunks);

#pragma unroll
        for (int ks = 0; ks < 2; ks++) {
            if (do_issue)
                issue_g1_part(nj, ks, tid, m0, n0, K, A, B, sbase);

            uint32_t kb = ks * 32;
            uint32_t a[2][4];
#pragma unroll
            for (int i = 0; i < 2; i++) {
                uint32_t off = SWZ2(arowr[i] + kb);
                LDSM4(a[i][0], a[i][1], a[i][2], a[i][3], st + G1_A + off);
            }
#pragma unroll
            for (int p = 0; p < 4; p++) {
                uint32_t off = SWZ2(browr[p] + kb);
                uint32_t b0, b1, b2, b3;
                LDSM4(b0, b1, b2, b3, st + G1_B + off);
#pragma unroll
                for (int i = 0; i < 2; i++) {
                    mma16816(acc[i][2 * p],     a[i], b0, b1);
                    mma16816(acc[i][2 * p + 1], a[i], b2, b3);
                }
            }
        }
        CP_COMMIT();
    }

    const int g   = lane >> 2;
    const int tig = lane & 3;
#pragma unroll
    for (int i = 0; i < 2; i++) {
        int row = m0 + wm * 32 + i * 16 + g;
#pragma unroll
        for (int j = 0; j < 8; j++) {
            int col = n0 + wn * 64 + j * 8 + 2 * tig;
            *(float2*)&C[(size_t)row * N + col] =
                make_float2(acc[i][j][0], acc[i][j][1]);
            *(float2*)&C[(size_t)(row + 8) * N + col] =
                make_float2(acc[i][j][2], acc[i][j][3]);
        }
    }
}

// ---------------------------------------------------------------------------
// Fused RoPE + fp16 hi/lo split. 256-thread blocks (4 head-units each).
// ---------------------------------------------------------------------------
__global__ __launch_bounds__(256) void rope_split_kernel()
{
    const int s = blockIdx.x;
    const int h = blockIdx.y * 4 + (threadIdx.x >> 6);
    const int i = threadIdx.x & 63;

    const float* p;
    h16 *oh, *ol;
    if (h < NH) {
        size_t base = (size_t)s * HID + h * HD;
        p = &g_Q[base]; oh = &g_Qh[base]; ol = &g_Ql[base];
    } else {
        size_t base = (size_t)s * KVDIM + (h - NH) * HD;
        p = &g_K[base]; oh = &g_Kh[base]; ol = &g_Kl[base];
    }

    float freq = __powf(10000.0f, -((float)(2 * i)) / 128.0f);
    float ang  = (float)s * freq;
    float sn, c;
    sincosf(ang, &sn, &c);

    float x1 = p[i];
    float x2 = p[i + 64];
    float y1 = x1 * c - x2 * sn;
    float y2 = x2 * c + x1 * sn;

    h16 h1 = __float2half(y1);
    h16 h2 = __float2half(y2);
    oh[i]      = h1;
    oh[i + 64] = h2;
    ol[i]      = __float2half(y1 - __half2float(h1));
    ol[i + 64] = __float2half(y2 - __half2float(h2));
}

// ---------------------------------------------------------------------------
// HMMA flash attention: QK^T 3-product (accumulator-major), PV 1-product.
// 3-stage KV pipeline, single sync per tile, reversed qt order. (R12/R16)
// ---------------------------------------------------------------------------
#define F_QH 0
#define F_QL 32768
#define F_KV 65536
#define KVSTG 49152
#define FLASH_SMEM (F_KV + 3 * KVSTG)   // 212992

__device__ __forceinline__ void flash_issue_kv(int jt, int tid, int kvh, uint32_t sbase)
{
    uint32_t st = sbase + F_KV + (jt % 3) * KVSTG;
#pragma unroll
    for (int t = 0; t < 12; t++) {
        int idx = tid + t * 256;
        int tile = idx >> 10;                 // 0:Kh 1:Kl 2:V
        int r    = (idx >> 4) & 63;
        int ch   = idx & 15;
        uint32_t off = SWZV((uint32_t)(r * 256 + ch * 16));
        size_t gsrc = (size_t)(jt * 64 + r) * KVDIM + kvh * HD + ch * 8;
        const h16* base = (tile == 0) ? g_Kh : (tile == 1) ? g_Kl : g_V16;
        CP_ASYNC16(st + tile * 16384 + off, base + gsrc);
    }
}

__global__ __launch_bounds__(256, 1) void flash_mma()
{
    extern __shared__ char smem[];
    const uint32_t sbase = smem_u32(smem);
    const int tid  = threadIdx.x;
    const int lane = tid & 31;
    const int wid  = tid >> 5;
    const int qt   = gridDim.x - 1 - blockIdx.x;   // heavy tiles first
    const int h    = blockIdx.y;
    const int kvh  = h >> 2;
    const int q0   = qt * 128;
    const int g    = lane >> 2;
    const int tig  = lane & 3;

#pragma unroll
    for (int t = 0; t < 16; t++) {
        int idx = tid + t * 256;
        int tile = idx >> 11;
        int r    = (idx >> 4) & 127;
        int ch   = idx & 15;
        uint32_t off = SWZV((uint32_t)(r * 256 + ch * 16));
        const h16* src = (tile ? g_Ql : g_Qh) + (size_t)(q0 + r) * HID + h * HD + ch * 8;
        CP_ASYNC16(sbase + (tile ? F_QL : F_QH) + off, src);
    }
    CP_COMMIT();

    const int ntiles = 2 * qt + 2;
    flash_issue_kv(0, tid, kvh, sbase);
    CP_COMMIT();
    flash_issue_kv(1, tid, kvh, sbase);
    CP_COMMIT();

    float of[16][4];
#pragma unroll
    for (int nt = 0; nt < 16; nt++)
#pragma unroll
        for (int r = 0; r < 4; r++) of[nt][r] = 0.f;
    float m0 = -INFINITY, m1 = -INFINITY, l0 = 0.f, l1 = 0.f;

    const float scale = 0.08838834764831845f;
    const int rg0 = q0 + wid * 16 + g;
    const int rg1 = rg0 + 8;

    uint32_t aoffQ = (uint32_t)((wid * 16 + (lane & 15)) * 256 + (lane >> 4) * 16);
    uint32_t boffK[4];
#pragma unroll
    for (int p = 0; p < 4; p++)
        boffK[p] = (uint32_t)((p * 16 + (lane & 7) + ((lane >> 4) << 3)) * 256 +
                              ((lane >> 3) & 1) * 16);
    uint32_t voffr = (uint32_t)(((lane & 7) + ((lane >> 3) & 1) * 8) * 256 +
                                (lane >> 4) * 16);

    for (int jt = 0; jt < ntiles; jt++) {
        uint32_t st = sbase + F_KV + (jt % 3) * KVSTG;
        CP_WAIT1();
        __syncthreads();

        int nj = jt + 2;
        if (nj < ntiles)
            flash_issue_kv(nj, tid, kvh, sbase);
        CP_COMMIT();

        // --- S = Qh*Kh^T + Ql*Kh^T + Qh*Kl^T ---
        float sfrag[8][4];
#pragma unroll
        for (int j = 0; j < 8; j++)
#pragma unroll
            for (int r = 0; r < 4; r++) sfrag[j][r] = 0.f;

#pragma unroll
        for (int ks = 0; ks < 8; ks++) {
            uint32_t kb = ks * 32;
            uint32_t qh[4], ql[4], kh[4][4], kl[4][4];
            uint32_t qo = SWZV(aoffQ + kb);
            LDSM4(qh[0], qh[1], qh[2], qh[3], sbase + F_QH + qo);
            LDSM4(ql[0], ql[1], ql[2], ql[3], sbase + F_QL + qo);
#pragma unroll
            for (int p = 0; p < 4; p++) {
                uint32_t ko = SWZV(boffK[p] + kb);
                LDSM4(kh[p][0], kh[p][1], kh[p][2], kh[p][3], st + 0 + ko);
                LDSM4(kl[p][0], kl[p][1], kl[p][2], kl[p][3], st + 16384 + ko);
            }
#pragma unroll
            for (int j = 0; j < 8; j++) {
                int p = j >> 1;
                int hs = (j & 1) << 1;
                mma16816(sfrag[j], qh, kh[p][hs], kh[p][hs + 1]);
                mma16816(sfrag[j], ql, kh[p][hs], kh[p][hs + 1]);
                mma16816(sfrag[j], qh, kl[p][hs], kl[p][hs + 1]);
            }
        }

#pragma unroll
        for (int j = 0; j < 8; j++) {
            int cg = jt * 64 + j * 8 + 2 * tig;
            float c0 = sfrag[j][0] * scale; if (cg     > rg0) c0 = -INFINITY;
            float c1 = sfrag[j][1] * scale; if (cg + 1 > rg0) c1 = -INFINITY;
            float c2 = sfrag[j][2] * scale; if (cg     > rg1) c2 = -INFINITY;
            float c3 = sfrag[j][3] * scale; if (cg + 1 > rg1) c3 = -INFINITY;
            sfrag[j][0] = c0; sfrag[j][1] = c1; sfrag[j][2] = c2; sfrag[j][3] = c3;
        }

        float mx0 = -INFINITY, mx1 = -INFINITY;
#pragma unroll
        for (int j = 0; j < 8; j++) {
            mx0 = fmaxf(mx0, fmaxf(sfrag[j][0], sfrag[j][1]));
            mx1 = fmaxf(mx1, fmaxf(sfrag[j][2], sfrag[j][3]));
        }
        mx0 = fmaxf(mx0, __shfl_xor_sync(0xffffffffu, mx0, 1));
        mx0 = fmaxf(mx0, __shfl_xor_sync(0xffffffffu, mx0, 2));
        mx1 = fmaxf(mx1, __shfl_xor_sync(0xffffffffu, mx1, 1));
        mx1 = fmaxf(mx1, __shfl_xor_sync(0xffffffffu, mx1, 2));
        float mn0 = fmaxf(m0, mx0);
        float mn1 = fmaxf(m1, mx1);
        float f0 = __expf(m0 - mn0);
        float f1 = __expf(m1 - mn1);

        // P single fp16 (PV 1-product)
        uint32_t ph0[8], ph1[8];
        float s0 = 0.f, s1 = 0.f;
#pragma unroll
        for (int j = 0; j < 8; j++) {
            float e0 = __expf(sfrag[j][0] - mn0);
            float e1 = __expf(sfrag[j][1] - mn0);
            float e2 = __expf(sfrag[j][2] - mn1);
            float e3 = __expf(sfrag[j][3] - mn1);
            s0 += e0 + e1; s1 += e2 + e3;
            ph0[j] = pack_h2(e0, e1);
            ph1[j] = pack_h2(e2, e3);
        }
        s0 += __shfl_xor_sync(0xffffffffu, s0, 1);
        s0 += __shfl_xor_sync(0xffffffffu, s0, 2);
        s1 += __shfl_xor_sync(0xffffffffu, s1, 1);
        s1 += __shfl_xor_sync(0xffffffffu, s1, 2);
        l0 = l0 * f0 + s0;
        l1 = l1 * f1 + s1;
        m0 = mn0; m1 = mn1;
#pragma unroll
        for (int nt = 0; nt < 16; nt++) {
            of[nt][0] *= f0; of[nt][1] *= f0;
            of[nt][2] *= f1; of[nt][3] *= f1;
        }

        // --- O += P*V (single product) ---
#pragma unroll
        for (int kk = 0; kk < 4; kk++) {
            uint32_t ah[4] = {ph0[2 * kk], ph1[2 * kk], ph0[2 * kk + 1], ph1[2 * kk + 1]};
#pragma unroll
            for (int np = 0; np < 8; np++) {
                uint32_t off = SWZV((uint32_t)(kk * 16 * 256) + voffr + (uint32_t)(np * 32));
                uint32_t v0, v1, v2, v3;
                LDSM4T(v0, v1, v2, v3, st + 32768 + off);
                mma16816(of[2 * np],     ah, v0, v1);
                mma16816(of[2 * np + 1], ah, v2, v3);
            }
        }
    }

    float inv0 = 1.f / l0;
    float inv1 = 1.f / l1;
#pragma unroll
    for (int nt = 0; nt < 16; nt++) {
        int col = h * HD + nt * 8 + 2 * tig;
        *(uint32_t*)&g_Ah[(size_t)rg0 * HID + col] =
            pack_h2(of[nt][0] * inv0, of[nt][1] * inv0);
        *(uint32_t*)&g_Ah[(size_t)rg1 * HID + col] =
            pack_h2(of[nt][2] * inv1, of[nt][3] * inv1);
    }
}

// ---------------------------------------------------------------------------
extern "C" void kernel_launch(void* const* d_in, const int* in_sizes, int n_in,
                              void* d_out, int out_size)
{
    const float* X  = (const float*)d_in[0];
    const float* Wq = (const float*)d_in[1];
    const float* Wk = (const float*)d_in[2];
    const float* Wv = (const float*)d_in[3];
    const float* Wo = (const float*)d_in[4];
    float* out = (float*)d_out;

    h16 *Wo16, *Ahp;
    cudaGetSymbolAddress((void**)&Wo16, g_Wo16);
    cudaGetSymbolAddress((void**)&Ahp,  g_Ah);

    cudaFuncSetAttribute(gemm3_qkv, cudaFuncAttributeMaxDynamicSharedMemorySize, GEMM3_SMEM);
    cudaFuncSetAttribute(gemm1, cudaFuncAttributeMaxDynamicSharedMemorySize, GEMM1_SMEM);
    cudaFuncSetAttribute(flash_mma, cudaFuncAttributeMaxDynamicSharedMemorySize, FLASH_SMEM);

    prep_kernel<<<PB_WO, 256>>>((const float4*)X, (const float4*)Wq,
                                (const float4*)Wk, (const float4*)Wv,
                                (const float4*)Wo);

    gemm3_qkv<<<dim3(NQKV / BN, S_LEN / BM), 256, GEMM3_SMEM>>>();

    rope_split_kernel<<<dim3(S_LEN, (NH + NKV) / 4), 256>>>();

    flash_mma<<<dim3(S_LEN / 128, NH), 256, FLASH_SMEM>>>();

    gemm1<<<dim3(HID / BN, S_LEN / BM), 256, GEMM1_SMEM>>>(Ahp, Wo16, out, S_LEN, HID, HID);
}